// round 6
// baseline (speedup 1.0000x reference)
#include <cuda_runtime.h>
#include <cuda_bf16.h>
#include <cstdint>

#define L_DIM 1024
#define N_DIM 4096
#define K_DIM 1024
#define NHEADS 4
#define NCHUNK 32

// ---------------- scratch (device globals; no allocs allowed) ----------------
__device__ float g_q[L_DIM * N_DIM];
__device__ float g_keys[NHEADS * L_DIM * N_DIM];
__device__ float g_partial[NCHUNK * NHEADS * N_DIM];
__device__ float g_weight[NHEADS * N_DIM];
__device__ float g_fused[L_DIM * N_DIM];

__device__ __nv_bfloat16 g_WL_hi[L_DIM * K_DIM],            g_WL_lo[L_DIM * K_DIM];
__device__ __nv_bfloat16 g_Wimg_hi[NHEADS * L_DIM * K_DIM], g_Wimg_lo[NHEADS * L_DIM * K_DIM];
__device__ __nv_bfloat16 g_Wf_hi[L_DIM * K_DIM],            g_Wf_lo[L_DIM * K_DIM];
__device__ __nv_bfloat16 g_PT_hi[N_DIM * K_DIM],            g_PT_lo[N_DIM * K_DIM];
__device__ __nv_bfloat16 g_IT_hi[N_DIM * K_DIM],            g_IT_lo[N_DIM * K_DIM];
__device__ __nv_bfloat16 g_FT_hi[N_DIM * K_DIM],            g_FT_lo[N_DIM * K_DIM];

// ---------------- PTX helpers (sm_80-portable only) ----------------
__device__ __forceinline__ uint32_t smem_u32(const void* p) {
    uint32_t r;
    asm("{ .reg .u64 t; cvta.to.shared.u64 t, %1; cvt.u32.u64 %0, t; }" : "=r"(r) : "l"(p));
    return r;
}
__device__ __forceinline__ void cp16(uint32_t dst, const void* src) {
    asm volatile("cp.async.cg.shared.global [%0], [%1], 16;" :: "r"(dst), "l"(src) : "memory");
}
__device__ __forceinline__ void cp_commit() {
    asm volatile("cp.async.commit_group;" ::: "memory");
}
__device__ __forceinline__ void cp_wait1() {
    asm volatile("cp.async.wait_group 1;" ::: "memory");
}
__device__ __forceinline__ void cp_wait0() {
    asm volatile("cp.async.wait_group 0;" ::: "memory");
}
__device__ __forceinline__ void ldsm_x4(uint32_t& r0, uint32_t& r1, uint32_t& r2, uint32_t& r3,
                                        uint32_t addr) {
    asm volatile("ldmatrix.sync.aligned.m8n8.x4.shared.b16 {%0,%1,%2,%3}, [%4];"
                 : "=r"(r0), "=r"(r1), "=r"(r2), "=r"(r3) : "r"(addr));
}
__device__ __forceinline__ void mma_bf16(float* c, const uint32_t* a, uint32_t b0, uint32_t b1) {
    asm volatile(
        "mma.sync.aligned.m16n8k16.row.col.f32.bf16.bf16.f32 "
        "{%0,%1,%2,%3}, {%4,%5,%6,%7}, {%8,%9}, {%0,%1,%2,%3};"
        : "+f"(c[0]), "+f"(c[1]), "+f"(c[2]), "+f"(c[3])
        : "r"(a[0]), "r"(a[1]), "r"(a[2]), "r"(a[3]), "r"(b0), "r"(b1));
}

// ---------------- bf16x3 mma.sync GEMM body ----------------
// Packed layout: each 128B smem row = [hi k0..31 | lo k0..31] (chunks 0-3 hi, 4-7 lo).
// GBK=32, 3-stage ring, 32KB/stage -> 96KB smem -> 2 CTAs/SM.
#define GBM 128
#define GBN 128
#define GBK 32
#define OFF_B 16384
#define STAGE_B 32768
#define NSTAGE 3
#define GEMM_DSMEM (NSTAGE * STAGE_B)
#define KSTAGES (K_DIM / GBK)   // 32

__device__ __forceinline__ void gemm_body(
    const __nv_bfloat16* __restrict__ Ahi, const __nv_bfloat16* __restrict__ Alo,
    const __nv_bfloat16* __restrict__ Bhi, const __nv_bfloat16* __restrict__ Blo,
    const float* __restrict__ bias, float* __restrict__ C,
    int bm, int bn, uint32_t sbase)
{
    const int tid  = threadIdx.x;
    const int lane = tid & 31;
    const int wid  = tid >> 5;
    const int wm   = wid >> 1;
    const int wn   = wid & 1;

    // cp.async mapping: 1024 (row, chunk) slots; chunks 0-3 <- hi, 4-7 <- lo
    int crow[4], ccol[4];
    uint32_t cdst[4];
    #pragma unroll
    for (int t = 0; t < 4; t++) {
        int idx = (t << 8) + tid;
        int r = idx >> 3, c = idx & 7;
        crow[t] = r; ccol[t] = c;
        cdst[t] = (uint32_t)((r << 7) + ((c ^ (r & 7)) << 4));
    }

    auto issue_stage = [&](int kstage, int buf) {
        const uint32_t sb = sbase + buf * STAGE_B;
        const int k0 = kstage * GBK;
        #pragma unroll
        for (int t = 0; t < 4; t++) {
            const int r = crow[t], c = ccol[t];
            const int koff = k0 + ((c & 3) << 3);
            const __nv_bfloat16* asrc = (c < 4) ? (Ahi + (size_t)(bm + r) * K_DIM + koff)
                                                : (Alo + (size_t)(bm + r) * K_DIM + koff);
            const __nv_bfloat16* bsrc = (c < 4) ? (Bhi + (size_t)(bn + r) * K_DIM + koff)
                                                : (Blo + (size_t)(bn + r) * K_DIM + koff);
            cp16(sb + cdst[t], asrc);
            cp16(sb + OFF_B + cdst[t], bsrc);
        }
    };

    float acc[2][8][4];
    #pragma unroll
    for (int m = 0; m < 2; m++)
        #pragma unroll
        for (int n = 0; n < 8; n++)
            #pragma unroll
            for (int v = 0; v < 4; v++)
                acc[m][n][v] = 0.0f;

    const int a_row0 = wm * 32 + (lane & 15);
    const int a_ch0  = lane >> 4;                                  // 0..1
    const int b_row0 = wn * 64 + ((lane >> 4) << 3) + (lane & 7);
    const int b_ch0  = (lane >> 3) & 1;                            // 0..1

    issue_stage(0, 0); cp_commit();
    issue_stage(1, 1); cp_commit();

    int bc = 0;
    for (int i = 0; i < KSTAGES; i++) {
        if (i < KSTAGES - 1) cp_wait1(); else cp_wait0();
        __syncthreads();

        if (i + 2 < KSTAGES) {
            int bi = bc + 2; if (bi >= NSTAGE) bi -= NSTAGE;
            issue_stage(i + 2, bi);
            cp_commit();
        }

        const uint32_t st = sbase + bc * STAGE_B;
        #pragma unroll
        for (int ks = 0; ks < 2; ks++) {
            uint32_t ah[2][4], al[2][4], bh[4][4], bl[4][4];
            // load ah + bh
            #pragma unroll
            for (int mt = 0; mt < 2; mt++) {
                const int r = a_row0 + mt * 16;
                const int ch = ks * 2 + a_ch0;                      // hi chunk 0..3
                ldsm_x4(ah[mt][0], ah[mt][1], ah[mt][2], ah[mt][3],
                        st + (r << 7) + ((ch ^ (r & 7)) << 4));
            }
            #pragma unroll
            for (int np = 0; np < 4; np++) {
                const int r = b_row0 + np * 16;
                const int ch = ks * 2 + b_ch0;
                ldsm_x4(bh[np][0], bh[np][1], bh[np][2], bh[np][3],
                        st + OFF_B + (r << 7) + ((ch ^ (r & 7)) << 4));
            }
            // pass 1: Ahi * Bhi
            #pragma unroll
            for (int mt = 0; mt < 2; mt++)
                #pragma unroll
                for (int np = 0; np < 4; np++) {
                    mma_bf16(acc[mt][np * 2 + 0], ah[mt], bh[np][0], bh[np][1]);
                    mma_bf16(acc[mt][np * 2 + 1], ah[mt], bh[np][2], bh[np][3]);
                }
            // load al; pass 2: Alo * Bhi (bh dies after)
            #pragma unroll
            for (int mt = 0; mt < 2; mt++) {
                const int r = a_row0 + mt * 16;
                const int ch = ks * 2 + a_ch0 + 4;                  // lo chunk 4..7
                ldsm_x4(al[mt][0], al[mt][1], al[mt][2], al[mt][3],
                        st + (r << 7) + ((ch ^ (r & 7)) << 4));
            }
            #pragma unroll
            for (int mt = 0; mt < 2; mt++)
                #pragma unroll
                for (int np = 0; np < 4; np++) {
                    mma_bf16(acc[mt][np * 2 + 0], al[mt], bh[np][0], bh[np][1]);
                    mma_bf16(acc[mt][np * 2 + 1], al[mt], bh[np][2], bh[np][3]);
                }
            // load bl; pass 3: Ahi * Blo
            #pragma unroll
            for (int np = 0; np < 4; np++) {
                const int r = b_row0 + np * 16;
                const int ch = ks * 2 + b_ch0 + 4;
                ldsm_x4(bl[np][0], bl[np][1], bl[np][2], bl[np][3],
                        st + OFF_B + (r << 7) + ((ch ^ (r & 7)) << 4));
            }
            #pragma unroll
            for (int mt = 0; mt < 2; mt++)
                #pragma unroll
                for (int np = 0; np < 4; np++) {
                    mma_bf16(acc[mt][np * 2 + 0], ah[mt], bl[np][0], bl[np][1]);
                    mma_bf16(acc[mt][np * 2 + 1], ah[mt], bl[np][2], bl[np][3]);
                }
        }
        bc = (bc + 1 == NSTAGE) ? 0 : bc + 1;
    }

    #pragma unroll
    for (int mt = 0; mt < 2; mt++) {
        const int row = bm + wm * 32 + mt * 16 + (lane >> 2);
        const float bv0 = bias[row], bv8 = bias[row + 8];
        #pragma unroll
        for (int nt = 0; nt < 8; nt++) {
            const int col = bn + wn * 64 + nt * 8 + (lane & 3) * 2;
            float2 v0 = make_float2(acc[mt][nt][0] + bv0, acc[mt][nt][1] + bv0);
            float2 v1 = make_float2(acc[mt][nt][2] + bv8, acc[mt][nt][3] + bv8);
            *reinterpret_cast<float2*>(&C[(size_t)row * N_DIM + col])       = v0;
            *reinterpret_cast<float2*>(&C[(size_t)(row + 8) * N_DIM + col]) = v1;
        }
    }
}

__global__ __launch_bounds__(256, 2) void gemm_qk(
    const __nv_bfloat16* __restrict__ WLh, const __nv_bfloat16* __restrict__ WLl,
    const __nv_bfloat16* __restrict__ WIh, const __nv_bfloat16* __restrict__ WIl,
    const __nv_bfloat16* __restrict__ PTh, const __nv_bfloat16* __restrict__ PTl,
    const __nv_bfloat16* __restrict__ ITh, const __nv_bfloat16* __restrict__ ITl,
    const float* __restrict__ b_L, const float* __restrict__ b_img,
    float* __restrict__ q, float* __restrict__ keys)
{
    extern __shared__ char sm_raw[];
    const uint32_t sbase = smem_u32(sm_raw);
    const int by = blockIdx.y;
    if (by < 8) {
        gemm_body(WLh, WLl, PTh, PTl, b_L, q, by * GBM, blockIdx.x * GBN, sbase);
    } else {
        gemm_body(WIh, WIl, ITh, ITl, b_img, keys, (by - 8) * GBM, blockIdx.x * GBN, sbase);
    }
}

__global__ __launch_bounds__(256, 2) void gemm_f(
    const __nv_bfloat16* __restrict__ Ahi, const __nv_bfloat16* __restrict__ Alo,
    const __nv_bfloat16* __restrict__ Bhi, const __nv_bfloat16* __restrict__ Blo,
    const float* __restrict__ bias, float* __restrict__ C)
{
    extern __shared__ char sm_raw[];
    gemm_body(Ahi, Alo, Bhi, Blo, bias, C, blockIdx.y * GBM, blockIdx.x * GBN, smem_u32(sm_raw));
}

// ---------------- fused weight splits ----------------
__global__ __launch_bounds__(256) void split_all_w(
    const float* __restrict__ W_L, const float* __restrict__ W_img,
    const float* __restrict__ W_f,
    __nv_bfloat16* __restrict__ WLh, __nv_bfloat16* __restrict__ WLl,
    __nv_bfloat16* __restrict__ WIh, __nv_bfloat16* __restrict__ WIl,
    __nv_bfloat16* __restrict__ WFh, __nv_bfloat16* __restrict__ WFl)
{
    const int WSZ = L_DIM * K_DIM;
    int i = blockIdx.x * 256 + threadIdx.x;
    const float* src; __nv_bfloat16 *dh, *dl; int off;
    if (i < WSZ)                { src = W_L;   dh = WLh; dl = WLl; off = i; }
    else if (i < 5 * WSZ)       { src = W_img; dh = WIh; dl = WIl; off = i - WSZ; }
    else                        { src = W_f;   dh = WFh; dl = WFl; off = i - 5 * WSZ; }
    float v = src[off];
    __nv_bfloat16 h = __float2bfloat16(v);
    dh[off] = h;
    dl[off] = __float2bfloat16(v - __bfloat162float(h));
}

// ---------------- fp32 [K, N] -> bf16 hi/lo [N, K] split-transpose ----------------
__global__ __launch_bounds__(256) void split_transpose2(
    const float* __restrict__ X0, __nv_bfloat16* __restrict__ T0h, __nv_bfloat16* __restrict__ T0l,
    const float* __restrict__ X1, __nv_bfloat16* __restrict__ T1h, __nv_bfloat16* __restrict__ T1l)
{
    const float* X = (blockIdx.z == 0) ? X0 : X1;
    __nv_bfloat16* Th = (blockIdx.z == 0) ? T0h : T1h;
    __nv_bfloat16* Tl = (blockIdx.z == 0) ? T0l : T1l;
    __shared__ float t[32][33];
    int n0 = blockIdx.x * 32, k0 = blockIdx.y * 32;
    int tx = threadIdx.x & 31, ty = threadIdx.x >> 5;
    #pragma unroll
    for (int j = 0; j < 32; j += 8)
        t[ty + j][tx] = X[(size_t)(k0 + ty + j) * N_DIM + n0 + tx];
    __syncthreads();
    #pragma unroll
    for (int j = 0; j < 32; j += 8) {
        float v = t[tx][ty + j];
        __nv_bfloat16 h = __float2bfloat16(v);
        size_t o = (size_t)(n0 + ty + j) * K_DIM + k0 + tx;
        Th[o] = h;
        Tl[o] = __float2bfloat16(v - __bfloat162float(h));
    }
}

__global__ __launch_bounds__(256) void split_transpose1(
    const float* __restrict__ X, __nv_bfloat16* __restrict__ Th, __nv_bfloat16* __restrict__ Tl)
{
    __shared__ float t[32][33];
    int n0 = blockIdx.x * 32, k0 = blockIdx.y * 32;
    int tx = threadIdx.x & 31, ty = threadIdx.x >> 5;
    #pragma unroll
    for (int j = 0; j < 32; j += 8)
        t[ty + j][tx] = X[(size_t)(k0 + ty + j) * N_DIM + n0 + tx];
    __syncthreads();
    #pragma unroll
    for (int j = 0; j < 32; j += 8) {
        float v = t[tx][ty + j];
        __nv_bfloat16 h = __float2bfloat16(v);
        size_t o = (size_t)(n0 + ty + j) * K_DIM + k0 + tx;
        Th[o] = h;
        Tl[o] = __float2bfloat16(v - __bfloat162float(h));
    }
}

// ---------------- score partials (float4, 4 n per thread) ----------------
__global__ __launch_bounds__(256) void score_partial(
    const float* __restrict__ keys, const float* __restrict__ q,
    float* __restrict__ partial)
{
    const int n4    = (blockIdx.x * 256 + threadIdx.x) * 4;   // gridDim.x = 4
    const int chunk = blockIdx.y;                             // 32 chunks
    const int c0    = chunk * (L_DIM / NCHUNK);               // 32 rows per chunk

    float4 s[NHEADS];
    #pragma unroll
    for (int h = 0; h < NHEADS; h++) s[h] = make_float4(0.f, 0.f, 0.f, 0.f);

    #pragma unroll 2
    for (int c = c0; c < c0 + L_DIM / NCHUNK; c++) {
        const float4 qv = *reinterpret_cast<const float4*>(&q[(size_t)c * N_DIM + n4]);
        #pragma unroll
        for (int h = 0; h < NHEADS; h++) {
            const float4 kv = *reinterpret_cast<const float4*>(
                &keys[((size_t)(h * L_DIM + c)) * N_DIM + n4]);
            s[h].x += kv.x * qv.x; s[h].y += kv.y * qv.y;
            s[h].z += kv.z * qv.z; s[h].w += kv.w * qv.w;
        }
    }
    #pragma unroll
    for (int h = 0; h < NHEADS; h++)
        *reinterpret_cast<float4*>(&partial[((size_t)chunk * NHEADS + h) * N_DIM + n4]) = s[h];
}

// ---------------- softmax over heads (float4) ----------------
__global__ __launch_bounds__(256) void softmax_heads(
    const float* __restrict__ partial, float* __restrict__ weight,
    float* __restrict__ wmap_out)
{
    const int n4 = (blockIdx.x * 256 + threadIdx.x) * 4;      // gridDim.x = 4
    float4 s[NHEADS];
    #pragma unroll
    for (int h = 0; h < NHEADS; h++) s[h] = make_float4(0.f, 0.f, 0.f, 0.f);
    for (int ch = 0; ch < NCHUNK; ch++)
        #pragma unroll
        for (int h = 0; h < NHEADS; h++) {
            float4 p = *reinterpret_cast<const float4*>(
                &partial[((size_t)ch * NHEADS + h) * N_DIM + n4]);
            s[h].x += p.x; s[h].y += p.y; s[h].z += p.z; s[h].w += p.w;
        }

    const float inv_sqrt_dk = 1.0f / 32.0f;
    float sv[NHEADS][4];
    #pragma unroll
    for (int h = 0; h < NHEADS; h++) {
        sv[h][0] = s[h].x * inv_sqrt_dk; sv[h][1] = s[h].y * inv_sqrt_dk;
        sv[h][2] = s[h].z * inv_sqrt_dk; sv[h][3] = s[h].w * inv_sqrt_dk;
    }
    #pragma unroll
    for (int e = 0; e < 4; e++) {
        float m = -1e30f;
        #pragma unroll
        for (int h = 0; h < NHEADS; h++) m = fmaxf(m, sv[h][e]);
        float ex[NHEADS], sum = 0.f;
        #pragma unroll
        for (int h = 0; h < NHEADS; h++) { ex[h] = __expf(sv[h][e] - m); sum += ex[h]; }
        float inv = 1.0f / sum;
        #pragma unroll
        for (int h = 0; h < NHEADS; h++) sv[h][e] = ex[h] * inv;
    }
    #pragma unroll
    for (int h = 0; h < NHEADS; h++) {
        float4 w = make_float4(sv[h][0], sv[h][1], sv[h][2], sv[h][3]);
        *reinterpret_cast<float4*>(&weight[(size_t)h * N_DIM + n4])   = w;
        *reinterpret_cast<float4*>(&wmap_out[(size_t)h * N_DIM + n4]) = w;
    }
}

// ---------------- z + residual + LayerNorm (512 thr, float4, register-resident) -------
__global__ __launch_bounds__(512) void z_layernorm(
    const float* __restrict__ keys, const float* __restrict__ q,
    const float* __restrict__ weight, const float* __restrict__ gamma,
    const float* __restrict__ beta, float* __restrict__ fused)
{
    const int c = blockIdx.x;
    __shared__ float r1[16], r2[16];
    __shared__ float s_mean, s_rstd;

    float v[2][4];
    float lsum = 0.f, lsq = 0.f;
    #pragma unroll
    for (int j = 0; j < 2; j++) {
        const int n4 = (j * 512 + threadIdx.x) * 4;
        float4 qa = *reinterpret_cast<const float4*>(&q[(size_t)c * N_DIM + n4]);
        v[j][0] = qa.x; v[j][1] = qa.y; v[j][2] = qa.z; v[j][3] = qa.w;
        #pragma unroll
        for (int h = 0; h < NHEADS; h++) {
            float4 kv = *reinterpret_cast<const float4*>(
                &keys[((size_t)(h * L_DIM + c)) * N_DIM + n4]);
            float4 wv = *reinterpret_cast<const float4*>(&weight[(size_t)h * N_DIM + n4]);
            v[j][0] += wv.x * kv.x; v[j][1] += wv.y * kv.y;
            v[j][2] += wv.z * kv.z; v[j][3] += wv.w * kv.w;
        }
        #pragma unroll
        for (int e = 0; e < 4; e++) { lsum += v[j][e]; lsq += v[j][e] * v[j][e]; }
    }
    #pragma unroll
    for (int o = 16; o > 0; o >>= 1) {
        lsum += __shfl_xor_sync(0xffffffffu, lsum, o);
        lsq  += __shfl_xor_sync(0xffffffffu, lsq, o);
    }
    const int wid = threadIdx.x >> 5, lid = threadIdx.x & 31;
    if (lid == 0) { r1[wid] = lsum; r2[wid] = lsq; }
    __syncthreads();
    if (threadIdx.x == 0) {
        float ts = 0.f, tq = 0.f;
        #pragma unroll
        for (int i = 0; i < 16; i++) { ts += r1[i]; tq += r2[i]; }
        float mean = ts * (1.0f / N_DIM);
        float var  = tq * (1.0f / N_DIM) - mean * mean;
        s_mean = mean;
        s_rstd = rsqrtf(var + 1e-5f);
    }
    __syncthreads();
    const float mean = s_mean, rstd = s_rstd;
    #pragma unroll
    for (int j = 0; j < 2; j++) {
        const int n4 = (j * 512 + threadIdx.x) * 4;
        float4 ga = *reinterpret_cast<const float4*>(&gamma[n4]);
        float4 ba = *reinterpret_cast<const float4*>(&beta[n4]);
        float4 o;
        o.x = (v[j][0] - mean) * rstd * ga.x + ba.x;
        o.y = (v[j][1] - mean) * rstd * ga.y + ba.y;
        o.z = (v[j][2] - mean) * rstd * ga.z + ba.z;
        o.w = (v[j][3] - mean) * rstd * ga.w + ba.w;
        *reinterpret_cast<float4*>(&fused[(size_t)c * N_DIM + n4]) = o;
    }
}

// ---------------- launch ----------------
extern "C" void kernel_launch(void* const* d_in, const int* in_sizes, int n_in,
                              void* d_out, int out_size)
{
    const float* point = (const float*)d_in[0];
    const float* img   = (const float*)d_in[1];
    const float* W_img = (const float*)d_in[2];
    const float* b_img = (const float*)d_in[3];
    const float* W_L   = (const float*)d_in[4];
    const float* b_L   = (const float*)d_in[5];
    const float* ln_g  = (const float*)d_in[6];
    const float* ln_b  = (const float*)d_in[7];
    const float* W_f   = (const float*)d_in[8];
    const float* b_f   = (const float*)d_in[9];

    float* out  = (float*)d_out;
    float* wmap = out + (size_t)L_DIM * N_DIM;

    float *q, *keys, *partial, *weight, *fused;
    cudaGetSymbolAddress((void**)&q,       g_q);
    cudaGetSymbolAddress((void**)&keys,    g_keys);
    cudaGetSymbolAddress((void**)&partial, g_partial);
    cudaGetSymbolAddress((void**)&weight,  g_weight);
    cudaGetSymbolAddress((void**)&fused,   g_fused);

    __nv_bfloat16 *WLh, *WLl, *WIh, *WIl, *WFh, *WFl, *PTh, *PTl, *ITh, *ITl, *FTh, *FTl;
    cudaGetSymbolAddress((void**)&WLh, g_WL_hi);   cudaGetSymbolAddress((void**)&WLl, g_WL_lo);
    cudaGetSymbolAddress((void**)&WIh, g_Wimg_hi); cudaGetSymbolAddress((void**)&WIl, g_Wimg_lo);
    cudaGetSymbolAddress((void**)&WFh, g_Wf_hi);   cudaGetSymbolAddress((void**)&WFl, g_Wf_lo);
    cudaGetSymbolAddress((void**)&PTh, g_PT_hi);   cudaGetSymbolAddress((void**)&PTl, g_PT_lo);
    cudaGetSymbolAddress((void**)&ITh, g_IT_hi);   cudaGetSymbolAddress((void**)&ITl, g_IT_lo);
    cudaGetSymbolAddress((void**)&FTh, g_FT_hi);   cudaGetSymbolAddress((void**)&FTl, g_FT_lo);

    cudaFuncSetAttribute(gemm_qk, cudaFuncAttributeMaxDynamicSharedMemorySize, GEMM_DSMEM);
    cudaFuncSetAttribute(gemm_f,  cudaFuncAttributeMaxDynamicSharedMemorySize, GEMM_DSMEM);

    split_all_w<<<(6 * L_DIM * K_DIM) / 256, 256>>>(
        W_L, W_img, W_f, WLh, WLl, WIh, WIl, WFh, WFl);

    split_transpose2<<<dim3(N_DIM / 32, K_DIM / 32, 2), 256>>>(
        point, PTh, PTl, img, ITh, ITl);

    gemm_qk<<<dim3(N_DIM / GBN, 8 + 32), 256, GEMM_DSMEM>>>(
        WLh, WLl, WIh, WIl, PTh, PTl, ITh, ITl, b_L, b_img, q, keys);

    score_partial<<<dim3(4, NCHUNK), 256>>>(keys, q, partial);
    softmax_heads<<<4, 256>>>(partial, weight, wmap);
    z_layernorm<<<L_DIM, 512>>>(keys, q, weight, ln_g, ln_b, fused);

    split_transpose1<<<dim3(N_DIM / 32, K_DIM / 32), 256>>>(fused, FTh, FTl);

    gemm_f<<<dim3(N_DIM / GBN, L_DIM / GBM), 256, GEMM_DSMEM>>>(
        WFh, WFl, FTh, FTl, b_f, out);
}

// round 7
// speedup vs baseline: 1.1174x; 1.1174x over previous
#include <cuda_runtime.h>
#include <cuda_bf16.h>
#include <cstdint>

#define L_DIM 1024
#define N_DIM 4096
#define K_DIM 1024
#define NHEADS 4
#define NCHUNK 64

// ---------------- scratch (device globals; no allocs allowed) ----------------
__device__ float g_q[L_DIM * N_DIM];
__device__ float g_keys[NHEADS * L_DIM * N_DIM];
__device__ float g_partial[NCHUNK * NHEADS * N_DIM];
__device__ float g_weight[NHEADS * N_DIM];
__device__ float g_fused[L_DIM * N_DIM];

__device__ __nv_bfloat16 g_WL_hi[L_DIM * K_DIM],            g_WL_lo[L_DIM * K_DIM];
__device__ __nv_bfloat16 g_Wimg_hi[NHEADS * L_DIM * K_DIM], g_Wimg_lo[NHEADS * L_DIM * K_DIM];
__device__ __nv_bfloat16 g_Wf_hi[L_DIM * K_DIM],            g_Wf_lo[L_DIM * K_DIM];
__device__ __nv_bfloat16 g_PT_hi[N_DIM * K_DIM],            g_PT_lo[N_DIM * K_DIM];
__device__ __nv_bfloat16 g_IT_hi[N_DIM * K_DIM],            g_IT_lo[N_DIM * K_DIM];
__device__ __nv_bfloat16 g_FT_hi[N_DIM * K_DIM],            g_FT_lo[N_DIM * K_DIM];

// ---------------- PTX helpers (sm_80-portable only) ----------------
__device__ __forceinline__ uint32_t smem_u32(const void* p) {
    uint32_t r;
    asm("{ .reg .u64 t; cvta.to.shared.u64 t, %1; cvt.u32.u64 %0, t; }" : "=r"(r) : "l"(p));
    return r;
}
__device__ __forceinline__ void cp16(uint32_t dst, const void* src) {
    asm volatile("cp.async.cg.shared.global [%0], [%1], 16;" :: "r"(dst), "l"(src) : "memory");
}
__device__ __forceinline__ void cp_commit() {
    asm volatile("cp.async.commit_group;" ::: "memory");
}
__device__ __forceinline__ void cp_wait1() {
    asm volatile("cp.async.wait_group 1;" ::: "memory");
}
__device__ __forceinline__ void cp_wait0() {
    asm volatile("cp.async.wait_group 0;" ::: "memory");
}
__device__ __forceinline__ void ldsm_x4(uint32_t& r0, uint32_t& r1, uint32_t& r2, uint32_t& r3,
                                        uint32_t addr) {
    asm volatile("ldmatrix.sync.aligned.m8n8.x4.shared.b16 {%0,%1,%2,%3}, [%4];"
                 : "=r"(r0), "=r"(r1), "=r"(r2), "=r"(r3) : "r"(addr));
}
__device__ __forceinline__ void mma_bf16(float* c, const uint32_t* a, uint32_t b0, uint32_t b1) {
    asm volatile(
        "mma.sync.aligned.m16n8k16.row.col.f32.bf16.bf16.f32 "
        "{%0,%1,%2,%3}, {%4,%5,%6,%7}, {%8,%9}, {%0,%1,%2,%3};"
        : "+f"(c[0]), "+f"(c[1]), "+f"(c[2]), "+f"(c[3])
        : "r"(a[0]), "r"(a[1]), "r"(a[2]), "r"(a[3]), "r"(b0), "r"(b1));
}

// ---------------- bf16x3 mma.sync GEMM body (3-stage cp.async ring, GBK=64) ------------
#define GBM 128
#define GBN 128
#define GBK 64
#define OFF_AH 0
#define OFF_AL 16384
#define OFF_BH 32768
#define OFF_BL 49152
#define STAGE_B 65536
#define NSTAGE 3
#define GEMM_DSMEM (NSTAGE * STAGE_B)
#define KSTAGES (K_DIM / GBK)   // 16

__device__ __forceinline__ void gemm_body(
    const __nv_bfloat16* __restrict__ Ahi, const __nv_bfloat16* __restrict__ Alo,
    const __nv_bfloat16* __restrict__ Bhi, const __nv_bfloat16* __restrict__ Blo,
    const float* __restrict__ bias, float* __restrict__ C,
    int bm, int bn, uint32_t sbase)
{
    const int tid  = threadIdx.x;
    const int lane = tid & 31;
    const int wid  = tid >> 5;
    const int wm   = wid >> 1;
    const int wn   = wid & 1;

    int crow[4], ccol[4];
    uint32_t cdst[4];
    #pragma unroll
    for (int t = 0; t < 4; t++) {
        int idx = (t << 8) + tid;
        int r = idx >> 3, c = idx & 7;
        crow[t] = r; ccol[t] = c;
        cdst[t] = (uint32_t)((r << 7) + ((c ^ (r & 7)) << 4));
    }

    auto issue_stage = [&](int kstage, int buf) {
        const uint32_t sb = sbase + buf * STAGE_B;
        const int k0 = kstage * GBK;
        #pragma unroll
        for (int t = 0; t < 4; t++) {
            const int r = crow[t], c = ccol[t];
            const size_t ka = (size_t)(bm + r) * K_DIM + k0 + (c << 3);
            const size_t kb = (size_t)(bn + r) * K_DIM + k0 + (c << 3);
            cp16(sb + OFF_AH + cdst[t], Ahi + ka);
            cp16(sb + OFF_AL + cdst[t], Alo + ka);
            cp16(sb + OFF_BH + cdst[t], Bhi + kb);
            cp16(sb + OFF_BL + cdst[t], Blo + kb);
        }
    };

    float acc[2][8][4];
    #pragma unroll
    for (int m = 0; m < 2; m++)
        #pragma unroll
        for (int n = 0; n < 8; n++)
            #pragma unroll
            for (int v = 0; v < 4; v++)
                acc[m][n][v] = 0.0f;

    const int a_row0 = wm * 32 + (lane & 15);
    const int a_ch0  = lane >> 4;
    const int b_row0 = wn * 64 + ((lane >> 4) << 3) + (lane & 7);
    const int b_ch0  = (lane >> 3) & 1;

    issue_stage(0, 0); cp_commit();
    issue_stage(1, 1); cp_commit();

    int bc = 0;
    for (int i = 0; i < KSTAGES; i++) {
        if (i < KSTAGES - 1) cp_wait1(); else cp_wait0();
        __syncthreads();

        if (i + 2 < KSTAGES) {
            int bi = bc + 2; if (bi >= NSTAGE) bi -= NSTAGE;
            issue_stage(i + 2, bi);
            cp_commit();
        }

        const uint32_t st = sbase + bc * STAGE_B;
        #pragma unroll
        for (int ks = 0; ks < 4; ks++) {
            uint32_t ah[2][4], al[2][4], bh[4][4], bl[4][4];
            #pragma unroll
            for (int mt = 0; mt < 2; mt++) {
                const int r = a_row0 + mt * 16;
                const int ch = ks * 2 + a_ch0;
                const uint32_t ad = st + (r << 7) + (((ch ^ (r & 7))) << 4);
                ldsm_x4(ah[mt][0], ah[mt][1], ah[mt][2], ah[mt][3], ad + OFF_AH);
                ldsm_x4(al[mt][0], al[mt][1], al[mt][2], al[mt][3], ad + OFF_AL);
            }
            #pragma unroll
            for (int np = 0; np < 4; np++) {
                const int r = b_row0 + np * 16;
                const int ch = ks * 2 + b_ch0;
                const uint32_t bd = st + (r << 7) + (((ch ^ (r & 7))) << 4);
                ldsm_x4(bh[np][0], bh[np][1], bh[np][2], bh[np][3], bd + OFF_BH);
                ldsm_x4(bl[np][0], bl[np][1], bl[np][2], bl[np][3], bd + OFF_BL);
            }
            #pragma unroll
            for (int mt = 0; mt < 2; mt++)
                #pragma unroll
                for (int np = 0; np < 4; np++) {
                    mma_bf16(acc[mt][np * 2 + 0], ah[mt], bh[np][0], bh[np][1]);
                    mma_bf16(acc[mt][np * 2 + 1], ah[mt], bh[np][2], bh[np][3]);
                }
            #pragma unroll
            for (int mt = 0; mt < 2; mt++)
                #pragma unroll
                for (int np = 0; np < 4; np++) {
                    mma_bf16(acc[mt][np * 2 + 0], ah[mt], bl[np][0], bl[np][1]);
                    mma_bf16(acc[mt][np * 2 + 1], ah[mt], bl[np][2], bl[np][3]);
                }
            #pragma unroll
            for (int mt = 0; mt < 2; mt++)
                #pragma unroll
                for (int np = 0; np < 4; np++) {
                    mma_bf16(acc[mt][np * 2 + 0], al[mt], bh[np][0], bh[np][1]);
                    mma_bf16(acc[mt][np * 2 + 1], al[mt], bh[np][2], bh[np][3]);
                }
        }
        bc = (bc + 1 == NSTAGE) ? 0 : bc + 1;
    }

    #pragma unroll
    for (int mt = 0; mt < 2; mt++) {
        const int row = bm + wm * 32 + mt * 16 + (lane >> 2);
        const float bv0 = bias[row], bv8 = bias[row + 8];
        #pragma unroll
        for (int nt = 0; nt < 8; nt++) {
            const int col = bn + wn * 64 + nt * 8 + (lane & 3) * 2;
            float2 v0 = make_float2(acc[mt][nt][0] + bv0, acc[mt][nt][1] + bv0);
            float2 v1 = make_float2(acc[mt][nt][2] + bv8, acc[mt][nt][3] + bv8);
            *reinterpret_cast<float2*>(&C[(size_t)row * N_DIM + col])       = v0;
            *reinterpret_cast<float2*>(&C[(size_t)(row + 8) * N_DIM + col]) = v1;
        }
    }
}

__global__ __launch_bounds__(256, 1) void gemm_qk(
    const __nv_bfloat16* __restrict__ WLh, const __nv_bfloat16* __restrict__ WLl,
    const __nv_bfloat16* __restrict__ WIh, const __nv_bfloat16* __restrict__ WIl,
    const __nv_bfloat16* __restrict__ PTh, const __nv_bfloat16* __restrict__ PTl,
    const __nv_bfloat16* __restrict__ ITh, const __nv_bfloat16* __restrict__ ITl,
    const float* __restrict__ b_L, const float* __restrict__ b_img,
    float* __restrict__ q, float* __restrict__ keys)
{
    extern __shared__ char sm_raw[];
    const uint32_t sbase = smem_u32(sm_raw);
    const int by = blockIdx.y;
    if (by < 8) {
        gemm_body(WLh, WLl, PTh, PTl, b_L, q, by * GBM, blockIdx.x * GBN, sbase);
    } else {
        gemm_body(WIh, WIl, ITh, ITl, b_img, keys, (by - 8) * GBM, blockIdx.x * GBN, sbase);
    }
}

__global__ __launch_bounds__(256, 1) void gemm_f(
    const __nv_bfloat16* __restrict__ Ahi, const __nv_bfloat16* __restrict__ Alo,
    const __nv_bfloat16* __restrict__ Bhi, const __nv_bfloat16* __restrict__ Blo,
    const float* __restrict__ bias, float* __restrict__ C)
{
    extern __shared__ char sm_raw[];
    gemm_body(Ahi, Alo, Bhi, Blo, bias, C, blockIdx.y * GBM, blockIdx.x * GBN, smem_u32(sm_raw));
}

// ---------------- fused weight splits ----------------
__global__ __launch_bounds__(256) void split_all_w(
    const float* __restrict__ W_L, const float* __restrict__ W_img,
    const float* __restrict__ W_f,
    __nv_bfloat16* __restrict__ WLh, __nv_bfloat16* __restrict__ WLl,
    __nv_bfloat16* __restrict__ WIh, __nv_bfloat16* __restrict__ WIl,
    __nv_bfloat16* __restrict__ WFh, __nv_bfloat16* __restrict__ WFl)
{
    const int WSZ = L_DIM * K_DIM;
    int i = blockIdx.x * 256 + threadIdx.x;
    const float* src; __nv_bfloat16 *dh, *dl; int off;
    if (i < WSZ)                { src = W_L;   dh = WLh; dl = WLl; off = i; }
    else if (i < 5 * WSZ)       { src = W_img; dh = WIh; dl = WIl; off = i - WSZ; }
    else                        { src = W_f;   dh = WFh; dl = WFl; off = i - 5 * WSZ; }
    float v = src[off];
    __nv_bfloat16 h = __float2bfloat16(v);
    dh[off] = h;
    dl[off] = __float2bfloat16(v - __bfloat162float(h));
}

// ---------------- fp32 [K, N] -> bf16 hi/lo [N, K] split-transpose ----------------
__global__ __launch_bounds__(256) void split_transpose2(
    const float* __restrict__ X0, __nv_bfloat16* __restrict__ T0h, __nv_bfloat16* __restrict__ T0l,
    const float* __restrict__ X1, __nv_bfloat16* __restrict__ T1h, __nv_bfloat16* __restrict__ T1l)
{
    const float* X = (blockIdx.z == 0) ? X0 : X1;
    __nv_bfloat16* Th = (blockIdx.z == 0) ? T0h : T1h;
    __nv_bfloat16* Tl = (blockIdx.z == 0) ? T0l : T1l;
    __shared__ float t[32][33];
    int n0 = blockIdx.x * 32, k0 = blockIdx.y * 32;
    int tx = threadIdx.x & 31, ty = threadIdx.x >> 5;
    #pragma unroll
    for (int j = 0; j < 32; j += 8)
        t[ty + j][tx] = X[(size_t)(k0 + ty + j) * N_DIM + n0 + tx];
    __syncthreads();
    #pragma unroll
    for (int j = 0; j < 32; j += 8) {
        float v = t[tx][ty + j];
        __nv_bfloat16 h = __float2bfloat16(v);
        size_t o = (size_t)(n0 + ty + j) * K_DIM + k0 + tx;
        Th[o] = h;
        Tl[o] = __float2bfloat16(v - __bfloat162float(h));
    }
}

__global__ __launch_bounds__(256) void split_transpose1(
    const float* __restrict__ X, __nv_bfloat16* __restrict__ Th, __nv_bfloat16* __restrict__ Tl)
{
    __shared__ float t[32][33];
    int n0 = blockIdx.x * 32, k0 = blockIdx.y * 32;
    int tx = threadIdx.x & 31, ty = threadIdx.x >> 5;
    #pragma unroll
    for (int j = 0; j < 32; j += 8)
        t[ty + j][tx] = X[(size_t)(k0 + ty + j) * N_DIM + n0 + tx];
    __syncthreads();
    #pragma unroll
    for (int j = 0; j < 32; j += 8) {
        float v = t[tx][ty + j];
        __nv_bfloat16 h = __float2bfloat16(v);
        size_t o = (size_t)(n0 + ty + j) * K_DIM + k0 + tx;
        Th[o] = h;
        Tl[o] = __float2bfloat16(v - __bfloat162float(h));
    }
}

// ---------------- score partials: 1024 blocks, 16 c-rows each ----------------
__global__ __launch_bounds__(256) void score_partial(
    const float* __restrict__ keys, const float* __restrict__ q,
    float* __restrict__ partial)
{
    const int n     = blockIdx.x * 256 + threadIdx.x;   // gridDim.x = 16
    const int chunk = blockIdx.y;                       // 64 chunks
    const int c0    = chunk * (L_DIM / NCHUNK);         // 16 rows per chunk

    float s[NHEADS] = {0.f, 0.f, 0.f, 0.f};
    #pragma unroll 2
    for (int c = c0; c < c0 + L_DIM / NCHUNK; c++) {
        const float qv = __ldg(&q[(size_t)c * N_DIM + n]);
        #pragma unroll
        for (int h = 0; h < NHEADS; h++)
            s[h] += __ldg(&keys[((size_t)(h * L_DIM + c)) * N_DIM + n]) * qv;
    }
    #pragma unroll
    for (int h = 0; h < NHEADS; h++)
        partial[((size_t)chunk * NHEADS + h) * N_DIM + n] = s[h];
}

// ---------------- softmax over heads ----------------
__global__ __launch_bounds__(256) void softmax_heads(
    const float* __restrict__ partial, float* __restrict__ weight,
    float* __restrict__ wmap_out)
{
    int n = blockIdx.x * 256 + threadIdx.x;             // gridDim.x = 16
    float s[NHEADS] = {0.f, 0.f, 0.f, 0.f};
    for (int ch = 0; ch < NCHUNK; ch++)
        #pragma unroll
        for (int h = 0; h < NHEADS; h++)
            s[h] += partial[((size_t)ch * NHEADS + h) * N_DIM + n];
    const float inv_sqrt_dk = 1.0f / 32.0f;
    float m = -1e30f;
    #pragma unroll
    for (int h = 0; h < NHEADS; h++) { s[h] *= inv_sqrt_dk; m = fmaxf(m, s[h]); }
    float e[NHEADS], sum = 0.f;
    #pragma unroll
    for (int h = 0; h < NHEADS; h++) { e[h] = __expf(s[h] - m); sum += e[h]; }
    float inv = 1.0f / sum;
    #pragma unroll
    for (int h = 0; h < NHEADS; h++) {
        float wv = e[h] * inv;
        weight[(size_t)h * N_DIM + n]   = wv;
        wmap_out[(size_t)h * N_DIM + n] = wv;
    }
}

// ---------------- z + residual + LayerNorm (512 thr, float4, register-resident) -------
__global__ __launch_bounds__(512) void z_layernorm(
    const float* __restrict__ keys, const float* __restrict__ q,
    const float* __restrict__ weight, const float* __restrict__ gamma,
    const float* __restrict__ beta, float* __restrict__ fused)
{
    const int c = blockIdx.x;
    __shared__ float r1[16], r2[16];
    __shared__ float s_mean, s_rstd;

    float v[2][4];
    float lsum = 0.f, lsq = 0.f;
    #pragma unroll
    for (int j = 0; j < 2; j++) {
        const int n4 = (j * 512 + threadIdx.x) * 4;
        float4 qa = *reinterpret_cast<const float4*>(&q[(size_t)c * N_DIM + n4]);
        v[j][0] = qa.x; v[j][1] = qa.y; v[j][2] = qa.z; v[j][3] = qa.w;
        #pragma unroll
        for (int h = 0; h < NHEADS; h++) {
            float4 kv = *reinterpret_cast<const float4*>(
                &keys[((size_t)(h * L_DIM + c)) * N_DIM + n4]);
            float4 wv = *reinterpret_cast<const float4*>(&weight[(size_t)h * N_DIM + n4]);
            v[j][0] += wv.x * kv.x; v[j][1] += wv.y * kv.y;
            v[j][2] += wv.z * kv.z; v[j][3] += wv.w * kv.w;
        }
        #pragma unroll
        for (int e = 0; e < 4; e++) { lsum += v[j][e]; lsq += v[j][e] * v[j][e]; }
    }
    #pragma unroll
    for (int o = 16; o > 0; o >>= 1) {
        lsum += __shfl_xor_sync(0xffffffffu, lsum, o);
        lsq  += __shfl_xor_sync(0xffffffffu, lsq, o);
    }
    const int wid = threadIdx.x >> 5, lid = threadIdx.x & 31;
    if (lid == 0) { r1[wid] = lsum; r2[wid] = lsq; }
    __syncthreads();
    if (threadIdx.x == 0) {
        float ts = 0.f, tq = 0.f;
        #pragma unroll
        for (int i = 0; i < 16; i++) { ts += r1[i]; tq += r2[i]; }
        float mean = ts * (1.0f / N_DIM);
        float var  = tq * (1.0f / N_DIM) - mean * mean;
        s_mean = mean;
        s_rstd = rsqrtf(var + 1e-5f);
    }
    __syncthreads();
    const float mean = s_mean, rstd = s_rstd;
    #pragma unroll
    for (int j = 0; j < 2; j++) {
        const int n4 = (j * 512 + threadIdx.x) * 4;
        float4 ga = *reinterpret_cast<const float4*>(&gamma[n4]);
        float4 ba = *reinterpret_cast<const float4*>(&beta[n4]);
        float4 o;
        o.x = (v[j][0] - mean) * rstd * ga.x + ba.x;
        o.y = (v[j][1] - mean) * rstd * ga.y + ba.y;
        o.z = (v[j][2] - mean) * rstd * ga.z + ba.z;
        o.w = (v[j][3] - mean) * rstd * ga.w + ba.w;
        *reinterpret_cast<float4*>(&fused[(size_t)c * N_DIM + n4]) = o;
    }
}

// ---------------- launch ----------------
extern "C" void kernel_launch(void* const* d_in, const int* in_sizes, int n_in,
                              void* d_out, int out_size)
{
    const float* point = (const float*)d_in[0];
    const float* img   = (const float*)d_in[1];
    const float* W_img = (const float*)d_in[2];
    const float* b_img = (const float*)d_in[3];
    const float* W_L   = (const float*)d_in[4];
    const float* b_L   = (const float*)d_in[5];
    const float* ln_g  = (const float*)d_in[6];
    const float* ln_b  = (const float*)d_in[7];
    const float* W_f   = (const float*)d_in[8];
    const float* b_f   = (const float*)d_in[9];

    float* out  = (float*)d_out;
    float* wmap = out + (size_t)L_DIM * N_DIM;

    float *q, *keys, *partial, *weight, *fused;
    cudaGetSymbolAddress((void**)&q,       g_q);
    cudaGetSymbolAddress((void**)&keys,    g_keys);
    cudaGetSymbolAddress((void**)&partial, g_partial);
    cudaGetSymbolAddress((void**)&weight,  g_weight);
    cudaGetSymbolAddress((void**)&fused,   g_fused);

    __nv_bfloat16 *WLh, *WLl, *WIh, *WIl, *WFh, *WFl, *PTh, *PTl, *ITh, *ITl, *FTh, *FTl;
    cudaGetSymbolAddress((void**)&WLh, g_WL_hi);   cudaGetSymbolAddress((void**)&WLl, g_WL_lo);
    cudaGetSymbolAddress((void**)&WIh, g_Wimg_hi); cudaGetSymbolAddress((void**)&WIl, g_Wimg_lo);
    cudaGetSymbolAddress((void**)&WFh, g_Wf_hi);   cudaGetSymbolAddress((void**)&WFl, g_Wf_lo);
    cudaGetSymbolAddress((void**)&PTh, g_PT_hi);   cudaGetSymbolAddress((void**)&PTl, g_PT_lo);
    cudaGetSymbolAddress((void**)&ITh, g_IT_hi);   cudaGetSymbolAddress((void**)&ITl, g_IT_lo);
    cudaGetSymbolAddress((void**)&FTh, g_FT_hi);   cudaGetSymbolAddress((void**)&FTl, g_FT_lo);

    cudaFuncSetAttribute(gemm_qk, cudaFuncAttributeMaxDynamicSharedMemorySize, GEMM_DSMEM);
    cudaFuncSetAttribute(gemm_f,  cudaFuncAttributeMaxDynamicSharedMemorySize, GEMM_DSMEM);

    split_all_w<<<(6 * L_DIM * K_DIM) / 256, 256>>>(
        W_L, W_img, W_f, WLh, WLl, WIh, WIl, WFh, WFl);

    split_transpose2<<<dim3(N_DIM / 32, K_DIM / 32, 2), 256>>>(
        point, PTh, PTl, img, ITh, ITl);

    gemm_qk<<<dim3(N_DIM / GBN, 8 + 32), 256, GEMM_DSMEM>>>(
        WLh, WLl, WIh, WIl, PTh, PTl, ITh, ITl, b_L, b_img, q, keys);

    score_partial<<<dim3(N_DIM / 256, NCHUNK), 256>>>(keys, q, partial);
    softmax_heads<<<N_DIM / 256, 256>>>(partial, weight, wmap);
    z_layernorm<<<L_DIM, 512>>>(keys, q, weight, ln_g, ln_b, fused);

    split_transpose1<<<dim3(N_DIM / 32, K_DIM / 32), 256>>>(fused, FTh, FTl);

    gemm_f<<<dim3(N_DIM / GBN, L_DIM / GBM), 256, GEMM_DSMEM>>>(
        WFh, WFl, FTh, FTl, b_f, out);
}

// round 8
// speedup vs baseline: 1.4786x; 1.3233x over previous
#include <cuda_runtime.h>
#include <cuda_fp16.h>
#include <cstdint>

#define L_DIM 1024
#define N_DIM 4096
#define K_DIM 1024
#define NHEADS 4
#define NCHUNK 64

// ---------------- scratch (device globals; no allocs allowed) ----------------
__device__ float g_q[L_DIM * N_DIM];
__device__ float g_keys[NHEADS * L_DIM * N_DIM];
__device__ float g_partial[NCHUNK * NHEADS * N_DIM];
__device__ float g_weight[NHEADS * N_DIM];
__device__ float g_fused[L_DIM * N_DIM];

__device__ __half g_WL_hi[L_DIM * K_DIM],            g_WL_lo[L_DIM * K_DIM];
__device__ __half g_Wimg_hi[NHEADS * L_DIM * K_DIM], g_Wimg_lo[NHEADS * L_DIM * K_DIM];
__device__ __half g_Wf_hi[L_DIM * K_DIM],            g_Wf_lo[L_DIM * K_DIM];
__device__ __half g_PT[N_DIM * K_DIM];   // point^T, fp16 hi only
__device__ __half g_IT[N_DIM * K_DIM];   // img^T
__device__ __half g_FT[N_DIM * K_DIM];   // fused^T

// ---------------- PTX helpers (sm_80-portable only) ----------------
__device__ __forceinline__ uint32_t smem_u32(const void* p) {
    uint32_t r;
    asm("{ .reg .u64 t; cvta.to.shared.u64 t, %1; cvt.u32.u64 %0, t; }" : "=r"(r) : "l"(p));
    return r;
}
__device__ __forceinline__ void cp16(uint32_t dst, const void* src) {
    asm volatile("cp.async.cg.shared.global [%0], [%1], 16;" :: "r"(dst), "l"(src) : "memory");
}
__device__ __forceinline__ void cp_commit() {
    asm volatile("cp.async.commit_group;" ::: "memory");
}
__device__ __forceinline__ void cp_wait1() {
    asm volatile("cp.async.wait_group 1;" ::: "memory");
}
__device__ __forceinline__ void cp_wait0() {
    asm volatile("cp.async.wait_group 0;" ::: "memory");
}
__device__ __forceinline__ void ldsm_x4(uint32_t& r0, uint32_t& r1, uint32_t& r2, uint32_t& r3,
                                        uint32_t addr) {
    asm volatile("ldmatrix.sync.aligned.m8n8.x4.shared.b16 {%0,%1,%2,%3}, [%4];"
                 : "=r"(r0), "=r"(r1), "=r"(r2), "=r"(r3) : "r"(addr));
}
__device__ __forceinline__ void mma_f16(float* c, const uint32_t* a, uint32_t b0, uint32_t b1) {
    asm volatile(
        "mma.sync.aligned.m16n8k16.row.col.f32.f16.f16.f32 "
        "{%0,%1,%2,%3}, {%4,%5,%6,%7}, {%8,%9}, {%0,%1,%2,%3};"
        : "+f"(c[0]), "+f"(c[1]), "+f"(c[2]), "+f"(c[3])
        : "r"(a[0]), "r"(a[1]), "r"(a[2]), "r"(a[3]), "r"(b0), "r"(b1));
}

// ---------------- fp16x2 mma.sync GEMM body (2 passes, 3-stage cp.async ring) ----------
// C = (Ahi + Alo) * B^T + bias;  A fp16 hi/lo, B fp16 (hi only).
#define GBM 128
#define GBN 128
#define GBK 64
#define OFF_AH 0
#define OFF_AL 16384
#define OFF_B  32768
#define STAGE_B 49152
#define NSTAGE 3
#define GEMM_DSMEM (NSTAGE * STAGE_B)
#define KSTAGES (K_DIM / GBK)   // 16

__device__ __forceinline__ void gemm_body(
    const __half* __restrict__ Ahi, const __half* __restrict__ Alo,
    const __half* __restrict__ B,
    const float* __restrict__ bias, float* __restrict__ C,
    int bm, int bn, uint32_t sbase)
{
    const int tid  = threadIdx.x;
    const int lane = tid & 31;
    const int wid  = tid >> 5;
    const int wm   = wid >> 1;
    const int wn   = wid & 1;

    int crow[4], ccol[4];
    uint32_t cdst[4];
    #pragma unroll
    for (int t = 0; t < 4; t++) {
        int idx = (t << 8) + tid;
        int r = idx >> 3, c = idx & 7;
        crow[t] = r; ccol[t] = c;
        cdst[t] = (uint32_t)((r << 7) + ((c ^ (r & 7)) << 4));
    }

    auto issue_stage = [&](int kstage, int buf) {
        const uint32_t sb = sbase + buf * STAGE_B;
        const int k0 = kstage * GBK;
        #pragma unroll
        for (int t = 0; t < 4; t++) {
            const int r = crow[t], c = ccol[t];
            const size_t ka = (size_t)(bm + r) * K_DIM + k0 + (c << 3);
            const size_t kb = (size_t)(bn + r) * K_DIM + k0 + (c << 3);
            cp16(sb + OFF_AH + cdst[t], Ahi + ka);
            cp16(sb + OFF_AL + cdst[t], Alo + ka);
            cp16(sb + OFF_B  + cdst[t], B   + kb);
        }
    };

    float acc[2][8][4];
    #pragma unroll
    for (int m = 0; m < 2; m++)
        #pragma unroll
        for (int n = 0; n < 8; n++)
            #pragma unroll
            for (int v = 0; v < 4; v++)
                acc[m][n][v] = 0.0f;

    const int a_row0 = wm * 32 + (lane & 15);
    const int a_ch0  = lane >> 4;
    const int b_row0 = wn * 64 + ((lane >> 4) << 3) + (lane & 7);
    const int b_ch0  = (lane >> 3) & 1;

    issue_stage(0, 0); cp_commit();
    issue_stage(1, 1); cp_commit();

    int bc = 0;
    for (int i = 0; i < KSTAGES; i++) {
        if (i < KSTAGES - 1) cp_wait1(); else cp_wait0();
        __syncthreads();

        if (i + 2 < KSTAGES) {
            int bi = bc + 2; if (bi >= NSTAGE) bi -= NSTAGE;
            issue_stage(i + 2, bi);
            cp_commit();
        }

        const uint32_t st = sbase + bc * STAGE_B;
        #pragma unroll
        for (int ks = 0; ks < 4; ks++) {
            uint32_t ah[2][4], al[2][4], bh[4][4];
            #pragma unroll
            for (int mt = 0; mt < 2; mt++) {
                const int r = a_row0 + mt * 16;
                const int ch = ks * 2 + a_ch0;
                const uint32_t ad = st + (r << 7) + (((ch ^ (r & 7))) << 4);
                ldsm_x4(ah[mt][0], ah[mt][1], ah[mt][2], ah[mt][3], ad + OFF_AH);
                ldsm_x4(al[mt][0], al[mt][1], al[mt][2], al[mt][3], ad + OFF_AL);
            }
            #pragma unroll
            for (int np = 0; np < 4; np++) {
                const int r = b_row0 + np * 16;
                const int ch = ks * 2 + b_ch0;
                const uint32_t bd = st + (r << 7) + (((ch ^ (r & 7))) << 4);
                ldsm_x4(bh[np][0], bh[np][1], bh[np][2], bh[np][3], bd + OFF_B);
            }
            // pass 1: Ahi * B
            #pragma unroll
            for (int mt = 0; mt < 2; mt++)
                #pragma unroll
                for (int np = 0; np < 4; np++) {
                    mma_f16(acc[mt][np * 2 + 0], ah[mt], bh[np][0], bh[np][1]);
                    mma_f16(acc[mt][np * 2 + 1], ah[mt], bh[np][2], bh[np][3]);
                }
            // pass 2: Alo * B
            #pragma unroll
            for (int mt = 0; mt < 2; mt++)
                #pragma unroll
                for (int np = 0; np < 4; np++) {
                    mma_f16(acc[mt][np * 2 + 0], al[mt], bh[np][0], bh[np][1]);
                    mma_f16(acc[mt][np * 2 + 1], al[mt], bh[np][2], bh[np][3]);
                }
        }
        bc = (bc + 1 == NSTAGE) ? 0 : bc + 1;
    }

    #pragma unroll
    for (int mt = 0; mt < 2; mt++) {
        const int row = bm + wm * 32 + mt * 16 + (lane >> 2);
        const float bv0 = bias[row], bv8 = bias[row + 8];
        #pragma unroll
        for (int nt = 0; nt < 8; nt++) {
            const int col = bn + wn * 64 + nt * 8 + (lane & 3) * 2;
            float2 v0 = make_float2(acc[mt][nt][0] + bv0, acc[mt][nt][1] + bv0);
            float2 v1 = make_float2(acc[mt][nt][2] + bv8, acc[mt][nt][3] + bv8);
            *reinterpret_cast<float2*>(&C[(size_t)row * N_DIM + col])       = v0;
            *reinterpret_cast<float2*>(&C[(size_t)(row + 8) * N_DIM + col]) = v1;
        }
    }
}

__global__ __launch_bounds__(256, 1) void gemm_qk(
    const __half* __restrict__ WLh, const __half* __restrict__ WLl,
    const __half* __restrict__ WIh, const __half* __restrict__ WIl,
    const __half* __restrict__ PT,  const __half* __restrict__ IT,
    const float* __restrict__ b_L, const float* __restrict__ b_img,
    float* __restrict__ q, float* __restrict__ keys)
{
    extern __shared__ char sm_raw[];
    const uint32_t sbase = smem_u32(sm_raw);
    const int by = blockIdx.y;
    if (by < 8) {
        gemm_body(WLh, WLl, PT, b_L, q, by * GBM, blockIdx.x * GBN, sbase);
    } else {
        gemm_body(WIh, WIl, IT, b_img, keys, (by - 8) * GBM, blockIdx.x * GBN, sbase);
    }
}

__global__ __launch_bounds__(256, 1) void gemm_f(
    const __half* __restrict__ Ahi, const __half* __restrict__ Alo,
    const __half* __restrict__ B,
    const float* __restrict__ bias, float* __restrict__ C)
{
    extern __shared__ char sm_raw[];
    gemm_body(Ahi, Alo, B, bias, C, blockIdx.y * GBM, blockIdx.x * GBN, smem_u32(sm_raw));
}

// ---------------- fused weight splits (fp16 hi/lo) ----------------
__global__ __launch_bounds__(256) void split_all_w(
    const float* __restrict__ W_L, const float* __restrict__ W_img,
    const float* __restrict__ W_f,
    __half* __restrict__ WLh, __half* __restrict__ WLl,
    __half* __restrict__ WIh, __half* __restrict__ WIl,
    __half* __restrict__ WFh, __half* __restrict__ WFl)
{
    const int WSZ = L_DIM * K_DIM;
    int i = blockIdx.x * 256 + threadIdx.x;
    const float* src; __half *dh, *dl; int off;
    if (i < WSZ)                { src = W_L;   dh = WLh; dl = WLl; off = i; }
    else if (i < 5 * WSZ)       { src = W_img; dh = WIh; dl = WIl; off = i - WSZ; }
    else                        { src = W_f;   dh = WFh; dl = WFl; off = i - 5 * WSZ; }
    float v = src[off];
    __half h = __float2half(v);
    dh[off] = h;
    dl[off] = __float2half(v - __half2float(h));
}

// ---------------- fp32 [K, N] -> fp16 [N, K] transpose ----------------
__global__ __launch_bounds__(256) void trans_h2(
    const float* __restrict__ X0, __half* __restrict__ T0,
    const float* __restrict__ X1, __half* __restrict__ T1)
{
    const float* X = (blockIdx.z == 0) ? X0 : X1;
    __half* Th = (blockIdx.z == 0) ? T0 : T1;
    __shared__ float t[32][33];
    int n0 = blockIdx.x * 32, k0 = blockIdx.y * 32;
    int tx = threadIdx.x & 31, ty = threadIdx.x >> 5;
    #pragma unroll
    for (int j = 0; j < 32; j += 8)
        t[ty + j][tx] = X[(size_t)(k0 + ty + j) * N_DIM + n0 + tx];
    __syncthreads();
    #pragma unroll
    for (int j = 0; j < 32; j += 8)
        Th[(size_t)(n0 + ty + j) * K_DIM + k0 + tx] = __float2half(t[tx][ty + j]);
}

__global__ __launch_bounds__(256) void trans_h1(
    const float* __restrict__ X, __half* __restrict__ Th)
{
    __shared__ float t[32][33];
    int n0 = blockIdx.x * 32, k0 = blockIdx.y * 32;
    int tx = threadIdx.x & 31, ty = threadIdx.x >> 5;
    #pragma unroll
    for (int j = 0; j < 32; j += 8)
        t[ty + j][tx] = X[(size_t)(k0 + ty + j) * N_DIM + n0 + tx];
    __syncthreads();
    #pragma unroll
    for (int j = 0; j < 32; j += 8)
        Th[(size_t)(n0 + ty + j) * K_DIM + k0 + tx] = __float2half(t[tx][ty + j]);
}

// ---------------- score partials: 1024 blocks, 16 c-rows each ----------------
__global__ __launch_bounds__(256) void score_partial(
    const float* __restrict__ keys, const float* __restrict__ q,
    float* __restrict__ partial)
{
    const int n     = blockIdx.x * 256 + threadIdx.x;   // gridDim.x = 16
    const int chunk = blockIdx.y;                       // 64 chunks
    const int c0    = chunk * (L_DIM / NCHUNK);         // 16 rows per chunk

    float s[NHEADS] = {0.f, 0.f, 0.f, 0.f};
    #pragma unroll 2
    for (int c = c0; c < c0 + L_DIM / NCHUNK; c++) {
        const float qv = __ldg(&q[(size_t)c * N_DIM + n]);
        #pragma unroll
        for (int h = 0; h < NHEADS; h++)
            s[h] += __ldg(&keys[((size_t)(h * L_DIM + c)) * N_DIM + n]) * qv;
    }
    #pragma unroll
    for (int h = 0; h < NHEADS; h++)
        partial[((size_t)chunk * NHEADS + h) * N_DIM + n] = s[h];
}

// ---------------- softmax over heads ----------------
__global__ __launch_bounds__(256) void softmax_heads(
    const float* __restrict__ partial, float* __restrict__ weight,
    float* __restrict__ wmap_out)
{
    int n = blockIdx.x * 256 + threadIdx.x;
    float s[NHEADS] = {0.f, 0.f, 0.f, 0.f};
    for (int ch = 0; ch < NCHUNK; ch++)
        #pragma unroll
        for (int h = 0; h < NHEADS; h++)
            s[h] += partial[((size_t)ch * NHEADS + h) * N_DIM + n];
    const float inv_sqrt_dk = 1.0f / 32.0f;
    float m = -1e30f;
    #pragma unroll
    for (int h = 0; h < NHEADS; h++) { s[h] *= inv_sqrt_dk; m = fmaxf(m, s[h]); }
    float e[NHEADS], sum = 0.f;
    #pragma unroll
    for (int h = 0; h < NHEADS; h++) { e[h] = __expf(s[h] - m); sum += e[h]; }
    float inv = 1.0f / sum;
    #pragma unroll
    for (int h = 0; h < NHEADS; h++) {
        float wv = e[h] * inv;
        weight[(size_t)h * N_DIM + n]   = wv;
        wmap_out[(size_t)h * N_DIM + n] = wv;
    }
}

// ---------------- z + residual + LayerNorm (512 thr, float4, register-resident) -------
__global__ __launch_bounds__(512) void z_layernorm(
    const float* __restrict__ keys, const float* __restrict__ q,
    const float* __restrict__ weight, const float* __restrict__ gamma,
    const float* __restrict__ beta, float* __restrict__ fused)
{
    const int c = blockIdx.x;
    __shared__ float r1[16], r2[16];
    __shared__ float s_mean, s_rstd;

    float v[2][4];
    float lsum = 0.f, lsq = 0.f;
    #pragma unroll
    for (int j = 0; j < 2; j++) {
        const int n4 = (j * 512 + threadIdx.x) * 4;
        float4 qa = *reinterpret_cast<const float4*>(&q[(size_t)c * N_DIM + n4]);
        v[j][0] = qa.x; v[j][1] = qa.y; v[j][2] = qa.z; v[j][3] = qa.w;
        #pragma unroll
        for (int h = 0; h < NHEADS; h++) {
            float4 kv = *reinterpret_cast<const float4*>(
                &keys[((size_t)(h * L_DIM + c)) * N_DIM + n4]);
            float4 wv = *reinterpret_cast<const float4*>(&weight[(size_t)h * N_DIM + n4]);
            v[j][0] += wv.x * kv.x; v[j][1] += wv.y * kv.y;
            v[j][2] += wv.z * kv.z; v[j][3] += wv.w * kv.w;
        }
        #pragma unroll
        for (int e = 0; e < 4; e++) { lsum += v[j][e]; lsq += v[j][e] * v[j][e]; }
    }
    #pragma unroll
    for (int o = 16; o > 0; o >>= 1) {
        lsum += __shfl_xor_sync(0xffffffffu, lsum, o);
        lsq  += __shfl_xor_sync(0xffffffffu, lsq, o);
    }
    const int wid = threadIdx.x >> 5, lid = threadIdx.x & 31;
    if (lid == 0) { r1[wid] = lsum; r2[wid] = lsq; }
    __syncthreads();
    if (threadIdx.x == 0) {
        float ts = 0.f, tq = 0.f;
        #pragma unroll
        for (int i = 0; i < 16; i++) { ts += r1[i]; tq += r2[i]; }
        float mean = ts * (1.0f / N_DIM);
        float var  = tq * (1.0f / N_DIM) - mean * mean;
        s_mean = mean;
        s_rstd = rsqrtf(var + 1e-5f);
    }
    __syncthreads();
    const float mean = s_mean, rstd = s_rstd;
    #pragma unroll
    for (int j = 0; j < 2; j++) {
        const int n4 = (j * 512 + threadIdx.x) * 4;
        float4 ga = *reinterpret_cast<const float4*>(&gamma[n4]);
        float4 ba = *reinterpret_cast<const float4*>(&beta[n4]);
        float4 o;
        o.x = (v[j][0] - mean) * rstd * ga.x + ba.x;
        o.y = (v[j][1] - mean) * rstd * ga.y + ba.y;
        o.z = (v[j][2] - mean) * rstd * ga.z + ba.z;
        o.w = (v[j][3] - mean) * rstd * ga.w + ba.w;
        *reinterpret_cast<float4*>(&fused[(size_t)c * N_DIM + n4]) = o;
    }
}

// ---------------- launch ----------------
extern "C" void kernel_launch(void* const* d_in, const int* in_sizes, int n_in,
                              void* d_out, int out_size)
{
    const float* point = (const float*)d_in[0];
    const float* img   = (const float*)d_in[1];
    const float* W_img = (const float*)d_in[2];
    const float* b_img = (const float*)d_in[3];
    const float* W_L   = (const float*)d_in[4];
    const float* b_L   = (const float*)d_in[5];
    const float* ln_g  = (const float*)d_in[6];
    const float* ln_b  = (const float*)d_in[7];
    const float* W_f   = (const float*)d_in[8];
    const float* b_f   = (const float*)d_in[9];

    float* out  = (float*)d_out;
    float* wmap = out + (size_t)L_DIM * N_DIM;

    float *q, *keys, *partial, *weight, *fused;
    cudaGetSymbolAddress((void**)&q,       g_q);
    cudaGetSymbolAddress((void**)&keys,    g_keys);
    cudaGetSymbolAddress((void**)&partial, g_partial);
    cudaGetSymbolAddress((void**)&weight,  g_weight);
    cudaGetSymbolAddress((void**)&fused,   g_fused);

    __half *WLh, *WLl, *WIh, *WIl, *WFh, *WFl, *PT, *IT, *FT;
    cudaGetSymbolAddress((void**)&WLh, g_WL_hi);   cudaGetSymbolAddress((void**)&WLl, g_WL_lo);
    cudaGetSymbolAddress((void**)&WIh, g_Wimg_hi); cudaGetSymbolAddress((void**)&WIl, g_Wimg_lo);
    cudaGetSymbolAddress((void**)&WFh, g_Wf_hi);   cudaGetSymbolAddress((void**)&WFl, g_Wf_lo);
    cudaGetSymbolAddress((void**)&PT, g_PT);
    cudaGetSymbolAddress((void**)&IT, g_IT);
    cudaGetSymbolAddress((void**)&FT, g_FT);

    cudaFuncSetAttribute(gemm_qk, cudaFuncAttributeMaxDynamicSharedMemorySize, GEMM_DSMEM);
    cudaFuncSetAttribute(gemm_f,  cudaFuncAttributeMaxDynamicSharedMemorySize, GEMM_DSMEM);

    split_all_w<<<(6 * L_DIM * K_DIM) / 256, 256>>>(
        W_L, W_img, W_f, WLh, WLl, WIh, WIl, WFh, WFl);

    trans_h2<<<dim3(N_DIM / 32, K_DIM / 32, 2), 256>>>(point, PT, img, IT);

    gemm_qk<<<dim3(N_DIM / GBN, 8 + 32), 256, GEMM_DSMEM>>>(
        WLh, WLl, WIh, WIl, PT, IT, b_L, b_img, q, keys);

    score_partial<<<dim3(N_DIM / 256, NCHUNK), 256>>>(keys, q, partial);
    softmax_heads<<<N_DIM / 256, 256>>>(partial, weight, wmap);
    z_layernorm<<<L_DIM, 512>>>(keys, q, weight, ln_g, ln_b, fused);

    trans_h1<<<dim3(N_DIM / 32, K_DIM / 32), 256>>>(fused, FT);

    gemm_f<<<dim3(N_DIM / GBN, L_DIM / GBM), 256, GEMM_DSMEM>>>(
        WFh, WFl, FT, b_f, out);
}

// round 9
// speedup vs baseline: 1.5631x; 1.0572x over previous
#include <cuda_runtime.h>
#include <cuda_fp16.h>
#include <cstdint>

#define L_DIM 1024
#define N_DIM 4096
#define K_DIM 1024
#define NHEADS 4
#define NCHUNK 64

// ---------------- scratch (device globals; no allocs allowed) ----------------
__device__ float g_q[L_DIM * N_DIM];
__device__ float g_keys[NHEADS * L_DIM * N_DIM];
__device__ float g_partial[NCHUNK * NHEADS * N_DIM];
__device__ float g_weight[NHEADS * N_DIM];
__device__ float g_fused[L_DIM * N_DIM];

__device__ __half g_WL_hi[L_DIM * K_DIM],            g_WL_lo[L_DIM * K_DIM];
__device__ __half g_Wimg_hi[NHEADS * L_DIM * K_DIM], g_Wimg_lo[NHEADS * L_DIM * K_DIM];
__device__ __half g_Wf_hi[L_DIM * K_DIM],            g_Wf_lo[L_DIM * K_DIM];
__device__ __half g_PT[N_DIM * K_DIM];
__device__ __half g_IT[N_DIM * K_DIM];
__device__ __half g_FT[N_DIM * K_DIM];

// ---------------- PTX helpers (sm_80-portable only) ----------------
__device__ __forceinline__ uint32_t smem_u32(const void* p) {
    uint32_t r;
    asm("{ .reg .u64 t; cvta.to.shared.u64 t, %1; cvt.u32.u64 %0, t; }" : "=r"(r) : "l"(p));
    return r;
}
__device__ __forceinline__ void cp16(uint32_t dst, const void* src) {
    asm volatile("cp.async.cg.shared.global [%0], [%1], 16;" :: "r"(dst), "l"(src) : "memory");
}
__device__ __forceinline__ void cp_commit() {
    asm volatile("cp.async.commit_group;" ::: "memory");
}
__device__ __forceinline__ void cp_wait1() {
    asm volatile("cp.async.wait_group 1;" ::: "memory");
}
__device__ __forceinline__ void cp_wait0() {
    asm volatile("cp.async.wait_group 0;" ::: "memory");
}
__device__ __forceinline__ void ldsm_x4(uint32_t& r0, uint32_t& r1, uint32_t& r2, uint32_t& r3,
                                        uint32_t addr) {
    asm volatile("ldmatrix.sync.aligned.m8n8.x4.shared.b16 {%0,%1,%2,%3}, [%4];"
                 : "=r"(r0), "=r"(r1), "=r"(r2), "=r"(r3) : "r"(addr));
}
__device__ __forceinline__ void mma_f16(float* c, const uint32_t* a, uint32_t b0, uint32_t b1) {
    asm volatile(
        "mma.sync.aligned.m16n8k16.row.col.f32.f16.f16.f32 "
        "{%0,%1,%2,%3}, {%4,%5,%6,%7}, {%8,%9}, {%0,%1,%2,%3};"
        : "+f"(c[0]), "+f"(c[1]), "+f"(c[2]), "+f"(c[3])
        : "r"(a[0]), "r"(a[1]), "r"(a[2]), "r"(a[3]), "r"(b0), "r"(b1));
}

// ---------------- fp16x2 mma.sync GEMM body (2 passes, 2-stage ring, 2 CTAs/SM) --------
#define GBM 128
#define GBN 128
#define GBK 64
#define OFF_AH 0
#define OFF_AL 16384
#define OFF_B  32768
#define STAGE_B 49152
#define NSTAGE 2
#define GEMM_DSMEM (NSTAGE * STAGE_B)       // 96 KB -> 2 CTAs/SM
#define KSTAGES (K_DIM / GBK)               // 16

__device__ __forceinline__ void gemm_body(
    const __half* __restrict__ Ahi, const __half* __restrict__ Alo,
    const __half* __restrict__ B,
    const float* __restrict__ bias, float* __restrict__ C,
    int bm, int bn, uint32_t sbase)
{
    const int tid  = threadIdx.x;
    const int lane = tid & 31;
    const int wid  = tid >> 5;
    const int wm   = wid >> 1;
    const int wn   = wid & 1;

    int crow[4], ccol[4];
    uint32_t cdst[4];
    #pragma unroll
    for (int t = 0; t < 4; t++) {
        int idx = (t << 8) + tid;
        int r = idx >> 3, c = idx & 7;
        crow[t] = r; ccol[t] = c;
        cdst[t] = (uint32_t)((r << 7) + ((c ^ (r & 7)) << 4));
    }

    auto issue_stage = [&](int kstage, int buf) {
        const uint32_t sb = sbase + buf * STAGE_B;
        const int k0 = kstage * GBK;
        #pragma unroll
        for (int t = 0; t < 4; t++) {
            const int r = crow[t], c = ccol[t];
            const size_t ka = (size_t)(bm + r) * K_DIM + k0 + (c << 3);
            const size_t kb = (size_t)(bn + r) * K_DIM + k0 + (c << 3);
            cp16(sb + OFF_AH + cdst[t], Ahi + ka);
            cp16(sb + OFF_AL + cdst[t], Alo + ka);
            cp16(sb + OFF_B  + cdst[t], B   + kb);
        }
    };

    float acc[2][8][4];
    #pragma unroll
    for (int m = 0; m < 2; m++)
        #pragma unroll
        for (int n = 0; n < 8; n++)
            #pragma unroll
            for (int v = 0; v < 4; v++)
                acc[m][n][v] = 0.0f;

    const int a_row0 = wm * 32 + (lane & 15);
    const int a_ch0  = lane >> 4;
    const int b_row0 = wn * 64 + ((lane >> 4) << 3) + (lane & 7);
    const int b_ch0  = (lane >> 3) & 1;

    issue_stage(0, 0); cp_commit();
    issue_stage(1, 1); cp_commit();

    for (int i = 0; i < KSTAGES; i++) {
        const int p = i & 1;
        if (i < KSTAGES - 1) cp_wait1(); else cp_wait0();
        __syncthreads();                         // stage i landed in buf p

        const uint32_t st = sbase + p * STAGE_B;
        #pragma unroll
        for (int ks = 0; ks < 4; ks++) {
            uint32_t ah[2][4], al[2][4], bh[4][4];
            #pragma unroll
            for (int mt = 0; mt < 2; mt++) {
                const int r = a_row0 + mt * 16;
                const int ch = ks * 2 + a_ch0;
                const uint32_t ad = st + (r << 7) + (((ch ^ (r & 7))) << 4);
                ldsm_x4(ah[mt][0], ah[mt][1], ah[mt][2], ah[mt][3], ad + OFF_AH);
                ldsm_x4(al[mt][0], al[mt][1], al[mt][2], al[mt][3], ad + OFF_AL);
            }
            #pragma unroll
            for (int np = 0; np < 4; np++) {
                const int r = b_row0 + np * 16;
                const int ch = ks * 2 + b_ch0;
                const uint32_t bd = st + (r << 7) + (((ch ^ (r & 7))) << 4);
                ldsm_x4(bh[np][0], bh[np][1], bh[np][2], bh[np][3], bd + OFF_B);
            }
            #pragma unroll
            for (int mt = 0; mt < 2; mt++)
                #pragma unroll
                for (int np = 0; np < 4; np++) {
                    mma_f16(acc[mt][np * 2 + 0], ah[mt], bh[np][0], bh[np][1]);
                    mma_f16(acc[mt][np * 2 + 1], ah[mt], bh[np][2], bh[np][3]);
                }
            #pragma unroll
            for (int mt = 0; mt < 2; mt++)
                #pragma unroll
                for (int np = 0; np < 4; np++) {
                    mma_f16(acc[mt][np * 2 + 0], al[mt], bh[np][0], bh[np][1]);
                    mma_f16(acc[mt][np * 2 + 1], al[mt], bh[np][2], bh[np][3]);
                }
        }

        // all warps done with buf p before refilling it with stage i+2
        if (i + 2 < KSTAGES) {
            __syncthreads();
            issue_stage(i + 2, p);
            cp_commit();
        }
    }

    #pragma unroll
    for (int mt = 0; mt < 2; mt++) {
        const int row = bm + wm * 32 + mt * 16 + (lane >> 2);
        const float bv0 = bias[row], bv8 = bias[row + 8];
        #pragma unroll
        for (int nt = 0; nt < 8; nt++) {
            const int col = bn + wn * 64 + nt * 8 + (lane & 3) * 2;
            float2 v0 = make_float2(acc[mt][nt][0] + bv0, acc[mt][nt][1] + bv0);
            float2 v1 = make_float2(acc[mt][nt][2] + bv8, acc[mt][nt][3] + bv8);
            *reinterpret_cast<float2*>(&C[(size_t)row * N_DIM + col])       = v0;
            *reinterpret_cast<float2*>(&C[(size_t)(row + 8) * N_DIM + col]) = v1;
        }
    }
}

__global__ __launch_bounds__(256, 2) void gemm_qk(
    const __half* __restrict__ WLh, const __half* __restrict__ WLl,
    const __half* __restrict__ WIh, const __half* __restrict__ WIl,
    const __half* __restrict__ PT,  const __half* __restrict__ IT,
    const float* __restrict__ b_L, const float* __restrict__ b_img,
    float* __restrict__ q, float* __restrict__ keys)
{
    extern __shared__ char sm_raw[];
    const uint32_t sbase = smem_u32(sm_raw);
    const int by = blockIdx.y;
    if (by < 8) {
        gemm_body(WLh, WLl, PT, b_L, q, by * GBM, blockIdx.x * GBN, sbase);
    } else {
        gemm_body(WIh, WIl, IT, b_img, keys, (by - 8) * GBM, blockIdx.x * GBN, sbase);
    }
}

__global__ __launch_bounds__(256, 2) void gemm_f(
    const __half* __restrict__ Ahi, const __half* __restrict__ Alo,
    const __half* __restrict__ B,
    const float* __restrict__ bias, float* __restrict__ C)
{
    extern __shared__ char sm_raw[];
    gemm_body(Ahi, Alo, B, bias, C, blockIdx.y * GBM, blockIdx.x * GBN, smem_u32(sm_raw));
}

// ---------------- fused weight splits (fp16 hi/lo) ----------------
__global__ __launch_bounds__(256) void split_all_w(
    const float* __restrict__ W_L, const float* __restrict__ W_img,
    const float* __restrict__ W_f,
    __half* __restrict__ WLh, __half* __restrict__ WLl,
    __half* __restrict__ WIh, __half* __restrict__ WIl,
    __half* __restrict__ WFh, __half* __restrict__ WFl)
{
    const int WSZ = L_DIM * K_DIM;
    int i = blockIdx.x * 256 + threadIdx.x;
    const float* src; __half *dh, *dl; int off;
    if (i < WSZ)                { src = W_L;   dh = WLh; dl = WLl; off = i; }
    else if (i < 5 * WSZ)       { src = W_img; dh = WIh; dl = WIl; off = i - WSZ; }
    else                        { src = W_f;   dh = WFh; dl = WFl; off = i - 5 * WSZ; }
    float v = src[off];
    __half h = __float2half(v);
    dh[off] = h;
    dl[off] = __float2half(v - __half2float(h));
}

// ---------------- fp32 [K, N] -> fp16 [N, K] transpose ----------------
__global__ __launch_bounds__(256) void trans_h2(
    const float* __restrict__ X0, __half* __restrict__ T0,
    const float* __restrict__ X1, __half* __restrict__ T1)
{
    const float* X = (blockIdx.z == 0) ? X0 : X1;
    __half* Th = (blockIdx.z == 0) ? T0 : T1;
    __shared__ float t[32][33];
    int n0 = blockIdx.x * 32, k0 = blockIdx.y * 32;
    int tx = threadIdx.x & 31, ty = threadIdx.x >> 5;
    #pragma unroll
    for (int j = 0; j < 32; j += 8)
        t[ty + j][tx] = X[(size_t)(k0 + ty + j) * N_DIM + n0 + tx];
    __syncthreads();
    #pragma unroll
    for (int j = 0; j < 32; j += 8)
        Th[(size_t)(n0 + ty + j) * K_DIM + k0 + tx] = __float2half(t[tx][ty + j]);
}

__global__ __launch_bounds__(256) void trans_h1(
    const float* __restrict__ X, __half* __restrict__ Th)
{
    __shared__ float t[32][33];
    int n0 = blockIdx.x * 32, k0 = blockIdx.y * 32;
    int tx = threadIdx.x & 31, ty = threadIdx.x >> 5;
    #pragma unroll
    for (int j = 0; j < 32; j += 8)
        t[ty + j][tx] = X[(size_t)(k0 + ty + j) * N_DIM + n0 + tx];
    __syncthreads();
    #pragma unroll
    for (int j = 0; j < 32; j += 8)
        Th[(size_t)(n0 + ty + j) * K_DIM + k0 + tx] = __float2half(t[tx][ty + j]);
}

// ---------------- score partials: 1024 blocks, 16 c-rows each ----------------
__global__ __launch_bounds__(256) void score_partial(
    const float* __restrict__ keys, const float* __restrict__ q,
    float* __restrict__ partial)
{
    const int n     = blockIdx.x * 256 + threadIdx.x;
    const int chunk = blockIdx.y;
    const int c0    = chunk * (L_DIM / NCHUNK);

    float s[NHEADS] = {0.f, 0.f, 0.f, 0.f};
    #pragma unroll 2
    for (int c = c0; c < c0 + L_DIM / NCHUNK; c++) {
        const float qv = __ldg(&q[(size_t)c * N_DIM + n]);
        #pragma unroll
        for (int h = 0; h < NHEADS; h++)
            s[h] += __ldg(&keys[((size_t)(h * L_DIM + c)) * N_DIM + n]) * qv;
    }
    #pragma unroll
    for (int h = 0; h < NHEADS; h++)
        partial[((size_t)chunk * NHEADS + h) * N_DIM + n] = s[h];
}

// ---------------- softmax over heads ----------------
__global__ __launch_bounds__(256) void softmax_heads(
    const float* __restrict__ partial, float* __restrict__ weight,
    float* __restrict__ wmap_out)
{
    int n = blockIdx.x * 256 + threadIdx.x;
    float s[NHEADS] = {0.f, 0.f, 0.f, 0.f};
    for (int ch = 0; ch < NCHUNK; ch++)
        #pragma unroll
        for (int h = 0; h < NHEADS; h++)
            s[h] += partial[((size_t)ch * NHEADS + h) * N_DIM + n];
    const float inv_sqrt_dk = 1.0f / 32.0f;
    float m = -1e30f;
    #pragma unroll
    for (int h = 0; h < NHEADS; h++) { s[h] *= inv_sqrt_dk; m = fmaxf(m, s[h]); }
    float e[NHEADS], sum = 0.f;
    #pragma unroll
    for (int h = 0; h < NHEADS; h++) { e[h] = __expf(s[h] - m); sum += e[h]; }
    float inv = 1.0f / sum;
    #pragma unroll
    for (int h = 0; h < NHEADS; h++) {
        float wv = e[h] * inv;
        weight[(size_t)h * N_DIM + n]   = wv;
        wmap_out[(size_t)h * N_DIM + n] = wv;
    }
}

// ---------------- z + residual + LayerNorm ----------------
__global__ __launch_bounds__(512) void z_layernorm(
    const float* __restrict__ keys, const float* __restrict__ q,
    const float* __restrict__ weight, const float* __restrict__ gamma,
    const float* __restrict__ beta, float* __restrict__ fused)
{
    const int c = blockIdx.x;
    __shared__ float r1[16], r2[16];
    __shared__ float s_mean, s_rstd;

    float v[2][4];
    float lsum = 0.f, lsq = 0.f;
    #pragma unroll
    for (int j = 0; j < 2; j++) {
        const int n4 = (j * 512 + threadIdx.x) * 4;
        float4 qa = *reinterpret_cast<const float4*>(&q[(size_t)c * N_DIM + n4]);
        v[j][0] = qa.x; v[j][1] = qa.y; v[j][2] = qa.z; v[j][3] = qa.w;
        #pragma unroll
        for (int h = 0; h < NHEADS; h++) {
            float4 kv = *reinterpret_cast<const float4*>(
                &keys[((size_t)(h * L_DIM + c)) * N_DIM + n4]);
            float4 wv = *reinterpret_cast<const float4*>(&weight[(size_t)h * N_DIM + n4]);
            v[j][0] += wv.x * kv.x; v[j][1] += wv.y * kv.y;
            v[j][2] += wv.z * kv.z; v[j][3] += wv.w * kv.w;
        }
        #pragma unroll
        for (int e = 0; e < 4; e++) { lsum += v[j][e]; lsq += v[j][e] * v[j][e]; }
    }
    #pragma unroll
    for (int o = 16; o > 0; o >>= 1) {
        lsum += __shfl_xor_sync(0xffffffffu, lsum, o);
        lsq  += __shfl_xor_sync(0xffffffffu, lsq, o);
    }
    const int wid = threadIdx.x >> 5, lid = threadIdx.x & 31;
    if (lid == 0) { r1[wid] = lsum; r2[wid] = lsq; }
    __syncthreads();
    if (threadIdx.x == 0) {
        float ts = 0.f, tq = 0.f;
        #pragma unroll
        for (int i = 0; i < 16; i++) { ts += r1[i]; tq += r2[i]; }
        float mean = ts * (1.0f / N_DIM);
        float var  = tq * (1.0f / N_DIM) - mean * mean;
        s_mean = mean;
        s_rstd = rsqrtf(var + 1e-5f);
    }
    __syncthreads();
    const float mean = s_mean, rstd = s_rstd;
    #pragma unroll
    for (int j = 0; j < 2; j++) {
        const int n4 = (j * 512 + threadIdx.x) * 4;
        float4 ga = *reinterpret_cast<const float4*>(&gamma[n4]);
        float4 ba = *reinterpret_cast<const float4*>(&beta[n4]);
        float4 o;
        o.x = (v[j][0] - mean) * rstd * ga.x + ba.x;
        o.y = (v[j][1] - mean) * rstd * ga.y + ba.y;
        o.z = (v[j][2] - mean) * rstd * ga.z + ba.z;
        o.w = (v[j][3] - mean) * rstd * ga.w + ba.w;
        *reinterpret_cast<float4*>(&fused[(size_t)c * N_DIM + n4]) = o;
    }
}

// ---------------- launch ----------------
extern "C" void kernel_launch(void* const* d_in, const int* in_sizes, int n_in,
                              void* d_out, int out_size)
{
    const float* point = (const float*)d_in[0];
    const float* img   = (const float*)d_in[1];
    const float* W_img = (const float*)d_in[2];
    const float* b_img = (const float*)d_in[3];
    const float* W_L   = (const float*)d_in[4];
    const float* b_L   = (const float*)d_in[5];
    const float* ln_g  = (const float*)d_in[6];
    const float* ln_b  = (const float*)d_in[7];
    const float* W_f   = (const float*)d_in[8];
    const float* b_f   = (const float*)d_in[9];

    float* out  = (float*)d_out;
    float* wmap = out + (size_t)L_DIM * N_DIM;

    float *q, *keys, *partial, *weight, *fused;
    cudaGetSymbolAddress((void**)&q,       g_q);
    cudaGetSymbolAddress((void**)&keys,    g_keys);
    cudaGetSymbolAddress((void**)&partial, g_partial);
    cudaGetSymbolAddress((void**)&weight,  g_weight);
    cudaGetSymbolAddress((void**)&fused,   g_fused);

    __half *WLh, *WLl, *WIh, *WIl, *WFh, *WFl, *PT, *IT, *FT;
    cudaGetSymbolAddress((void**)&WLh, g_WL_hi);   cudaGetSymbolAddress((void**)&WLl, g_WL_lo);
    cudaGetSymbolAddress((void**)&WIh, g_Wimg_hi); cudaGetSymbolAddress((void**)&WIl, g_Wimg_lo);
    cudaGetSymbolAddress((void**)&WFh, g_Wf_hi);   cudaGetSymbolAddress((void**)&WFl, g_Wf_lo);
    cudaGetSymbolAddress((void**)&PT, g_PT);
    cudaGetSymbolAddress((void**)&IT, g_IT);
    cudaGetSymbolAddress((void**)&FT, g_FT);

    cudaFuncSetAttribute(gemm_qk, cudaFuncAttributeMaxDynamicSharedMemorySize, GEMM_DSMEM);
    cudaFuncSetAttribute(gemm_f,  cudaFuncAttributeMaxDynamicSharedMemorySize, GEMM_DSMEM);

    split_all_w<<<(6 * L_DIM * K_DIM) / 256, 256>>>(
        W_L, W_img, W_f, WLh, WLl, WIh, WIl, WFh, WFl);

    trans_h2<<<dim3(N_DIM / 32, K_DIM / 32, 2), 256>>>(point, PT, img, IT);

    gemm_qk<<<dim3(N_DIM / GBN, 8 + 32), 256, GEMM_DSMEM>>>(
        WLh, WLl, WIh, WIl, PT, IT, b_L, b_img, q, keys);

    score_partial<<<dim3(N_DIM / 256, NCHUNK), 256>>>(keys, q, partial);
    softmax_heads<<<N_DIM / 256, 256>>>(partial, weight, wmap);
    z_layernorm<<<L_DIM, 512>>>(keys, q, weight, ln_g, ln_b, fused);

    trans_h1<<<dim3(N_DIM / 32, K_DIM / 32), 256>>>(fused, FT);

    gemm_f<<<dim3(N_DIM / GBN, L_DIM / GBM), 256, GEMM_DSMEM>>>(
        WFh, WFl, FT, b_f, out);
}

// round 10
// speedup vs baseline: 2.4194x; 1.5478x over previous
#include <cuda_runtime.h>
#include <cuda_fp16.h>
#include <cstdint>

#define L_DIM 1024
#define N_DIM 4096
#define K_DIM 1024
#define NHEADS 4
#define NCHUNK 64

// ---------------- scratch (device globals; no allocs allowed) ----------------
__device__ float g_q[L_DIM * N_DIM];
__device__ float g_keys[NHEADS * L_DIM * N_DIM];
__device__ float g_partial[NCHUNK * NHEADS * N_DIM];
__device__ float g_weight[NHEADS * N_DIM];
__device__ float g_fused[L_DIM * N_DIM];

__device__ __half g_WL[L_DIM * K_DIM];
__device__ __half g_Wimg[NHEADS * L_DIM * K_DIM];
__device__ __half g_Wf[L_DIM * K_DIM];
__device__ __half g_PT[N_DIM * K_DIM];
__device__ __half g_IT[N_DIM * K_DIM];
__device__ __half g_FT[N_DIM * K_DIM];

// ---------------- PTX helpers (sm_80-portable only) ----------------
__device__ __forceinline__ uint32_t smem_u32(const void* p) {
    uint32_t r;
    asm("{ .reg .u64 t; cvta.to.shared.u64 t, %1; cvt.u32.u64 %0, t; }" : "=r"(r) : "l"(p));
    return r;
}
__device__ __forceinline__ void cp16(uint32_t dst, const void* src) {
    asm volatile("cp.async.cg.shared.global [%0], [%1], 16;" :: "r"(dst), "l"(src) : "memory");
}
__device__ __forceinline__ void cp_commit() {
    asm volatile("cp.async.commit_group;" ::: "memory");
}
__device__ __forceinline__ void cp_wait1() {
    asm volatile("cp.async.wait_group 1;" ::: "memory");
}
__device__ __forceinline__ void cp_wait0() {
    asm volatile("cp.async.wait_group 0;" ::: "memory");
}
__device__ __forceinline__ void ldsm_x4(uint32_t& r0, uint32_t& r1, uint32_t& r2, uint32_t& r3,
                                        uint32_t addr) {
    asm volatile("ldmatrix.sync.aligned.m8n8.x4.shared.b16 {%0,%1,%2,%3}, [%4];"
                 : "=r"(r0), "=r"(r1), "=r"(r2), "=r"(r3) : "r"(addr));
}
__device__ __forceinline__ void mma_f16(float* c, const uint32_t* a, uint32_t b0, uint32_t b1) {
    asm volatile(
        "mma.sync.aligned.m16n8k16.row.col.f32.f16.f16.f32 "
        "{%0,%1,%2,%3}, {%4,%5,%6,%7}, {%8,%9}, {%0,%1,%2,%3};"
        : "+f"(c[0]), "+f"(c[1]), "+f"(c[2]), "+f"(c[3])
        : "r"(a[0]), "r"(a[1]), "r"(a[2]), "r"(a[3]), "r"(b0), "r"(b1));
}

// ---------------- fp16 single-pass mma.sync GEMM (3-stage ring, 2 CTAs/SM) ------------
#define GBM 128
#define GBN 128
#define GBK 64
#define OFF_A 0
#define OFF_B 16384
#define STAGE_B 32768
#define NSTAGE 3
#define GEMM_DSMEM (NSTAGE * STAGE_B)       // 96 KB -> 2 CTAs/SM
#define KSTAGES (K_DIM / GBK)               // 16

__device__ __forceinline__ void gemm_body(
    const __half* __restrict__ A, const __half* __restrict__ B,
    const float* __restrict__ bias, float* __restrict__ C,
    int bm, int bn, uint32_t sbase)
{
    const int tid  = threadIdx.x;
    const int lane = tid & 31;
    const int wid  = tid >> 5;
    const int wm   = wid >> 1;
    const int wn   = wid & 1;

    int crow[4], ccol[4];
    uint32_t cdst[4];
    #pragma unroll
    for (int t = 0; t < 4; t++) {
        int idx = (t << 8) + tid;
        int r = idx >> 3, c = idx & 7;
        crow[t] = r; ccol[t] = c;
        cdst[t] = (uint32_t)((r << 7) + ((c ^ (r & 7)) << 4));
    }

    auto issue_stage = [&](int kstage, int buf) {
        const uint32_t sb = sbase + buf * STAGE_B;
        const int k0 = kstage * GBK;
        #pragma unroll
        for (int t = 0; t < 4; t++) {
            const int r = crow[t], c = ccol[t];
            cp16(sb + OFF_A + cdst[t], A + (size_t)(bm + r) * K_DIM + k0 + (c << 3));
            cp16(sb + OFF_B + cdst[t], B + (size_t)(bn + r) * K_DIM + k0 + (c << 3));
        }
    };

    float acc[2][8][4];
    #pragma unroll
    for (int m = 0; m < 2; m++)
        #pragma unroll
        for (int n = 0; n < 8; n++)
            #pragma unroll
            for (int v = 0; v < 4; v++)
                acc[m][n][v] = 0.0f;

    const int a_row0 = wm * 32 + (lane & 15);
    const int a_ch0  = lane >> 4;
    const int b_row0 = wn * 64 + ((lane >> 4) << 3) + (lane & 7);
    const int b_ch0  = (lane >> 3) & 1;

    issue_stage(0, 0); cp_commit();
    issue_stage(1, 1); cp_commit();

    int bc = 0;
    for (int i = 0; i < KSTAGES; i++) {
        if (i < KSTAGES - 1) cp_wait1(); else cp_wait0();
        __syncthreads();

        if (i + 2 < KSTAGES) {
            int bi = bc + 2; if (bi >= NSTAGE) bi -= NSTAGE;
            issue_stage(i + 2, bi);
            cp_commit();
        }

        const uint32_t st = sbase + bc * STAGE_B;
        #pragma unroll
        for (int ks = 0; ks < 4; ks++) {
            uint32_t ah[2][4], bh[4][4];
            #pragma unroll
            for (int mt = 0; mt < 2; mt++) {
                const int r = a_row0 + mt * 16;
                const int ch = ks * 2 + a_ch0;
                ldsm_x4(ah[mt][0], ah[mt][1], ah[mt][2], ah[mt][3],
                        st + OFF_A + (r << 7) + ((ch ^ (r & 7)) << 4));
            }
            #pragma unroll
            for (int np = 0; np < 4; np++) {
                const int r = b_row0 + np * 16;
                const int ch = ks * 2 + b_ch0;
                ldsm_x4(bh[np][0], bh[np][1], bh[np][2], bh[np][3],
                        st + OFF_B + (r << 7) + ((ch ^ (r & 7)) << 4));
            }
            #pragma unroll
            for (int mt = 0; mt < 2; mt++)
                #pragma unroll
                for (int np = 0; np < 4; np++) {
                    mma_f16(acc[mt][np * 2 + 0], ah[mt], bh[np][0], bh[np][1]);
                    mma_f16(acc[mt][np * 2 + 1], ah[mt], bh[np][2], bh[np][3]);
                }
        }
        bc = (bc + 1 == NSTAGE) ? 0 : bc + 1;
    }

    #pragma unroll
    for (int mt = 0; mt < 2; mt++) {
        const int row = bm + wm * 32 + mt * 16 + (lane >> 2);
        const float bv0 = bias[row], bv8 = bias[row + 8];
        #pragma unroll
        for (int nt = 0; nt < 8; nt++) {
            const int col = bn + wn * 64 + nt * 8 + (lane & 3) * 2;
            float2 v0 = make_float2(acc[mt][nt][0] + bv0, acc[mt][nt][1] + bv0);
            float2 v1 = make_float2(acc[mt][nt][2] + bv8, acc[mt][nt][3] + bv8);
            *reinterpret_cast<float2*>(&C[(size_t)row * N_DIM + col])       = v0;
            *reinterpret_cast<float2*>(&C[(size_t)(row + 8) * N_DIM + col]) = v1;
        }
    }
}

__global__ __launch_bounds__(256, 2) void gemm_qk(
    const __half* __restrict__ WL, const __half* __restrict__ WI,
    const __half* __restrict__ PT, const __half* __restrict__ IT,
    const float* __restrict__ b_L, const float* __restrict__ b_img,
    float* __restrict__ q, float* __restrict__ keys)
{
    extern __shared__ char sm_raw[];
    const uint32_t sbase = smem_u32(sm_raw);
    const int by = blockIdx.y;
    if (by < 8) {
        gemm_body(WL, PT, b_L, q, by * GBM, blockIdx.x * GBN, sbase);
    } else {
        gemm_body(WI, IT, b_img, keys, (by - 8) * GBM, blockIdx.x * GBN, sbase);
    }
}

__global__ __launch_bounds__(256, 2) void gemm_f(
    const __half* __restrict__ A, const __half* __restrict__ B,
    const float* __restrict__ bias, float* __restrict__ C)
{
    extern __shared__ char sm_raw[];
    gemm_body(A, B, bias, C, blockIdx.y * GBM, blockIdx.x * GBN, smem_u32(sm_raw));
}

// ---------------- fused weight convert (fp32 -> fp16) ----------------
__global__ __launch_bounds__(256) void convert_w(
    const float* __restrict__ W_L, const float* __restrict__ W_img,
    const float* __restrict__ W_f,
    __half* __restrict__ WL, __half* __restrict__ WI, __half* __restrict__ WF)
{
    const int WSZ = L_DIM * K_DIM;
    int i = blockIdx.x * 256 + threadIdx.x;
    const float* src; __half* dst; int off;
    if (i < WSZ)          { src = W_L;   dst = WL; off = i; }
    else if (i < 5 * WSZ) { src = W_img; dst = WI; off = i - WSZ; }
    else                  { src = W_f;   dst = WF; off = i - 5 * WSZ; }
    dst[off] = __float2half(src[off]);
}

// ---------------- fp32 [K, N] -> fp16 [N, K] transpose ----------------
__global__ __launch_bounds__(256) void trans_h2(
    const float* __restrict__ X0, __half* __restrict__ T0,
    const float* __restrict__ X1, __half* __restrict__ T1)
{
    const float* X = (blockIdx.z == 0) ? X0 : X1;
    __half* Th = (blockIdx.z == 0) ? T0 : T1;
    __shared__ float t[32][33];
    int n0 = blockIdx.x * 32, k0 = blockIdx.y * 32;
    int tx = threadIdx.x & 31, ty = threadIdx.x >> 5;
    #pragma unroll
    for (int j = 0; j < 32; j += 8)
        t[ty + j][tx] = X[(size_t)(k0 + ty + j) * N_DIM + n0 + tx];
    __syncthreads();
    #pragma unroll
    for (int j = 0; j < 32; j += 8)
        Th[(size_t)(n0 + ty + j) * K_DIM + k0 + tx] = __float2half(t[tx][ty + j]);
}

__global__ __launch_bounds__(256) void trans_h1(
    const float* __restrict__ X, __half* __restrict__ Th)
{
    __shared__ float t[32][33];
    int n0 = blockIdx.x * 32, k0 = blockIdx.y * 32;
    int tx = threadIdx.x & 31, ty = threadIdx.x >> 5;
    #pragma unroll
    for (int j = 0; j < 32; j += 8)
        t[ty + j][tx] = X[(size_t)(k0 + ty + j) * N_DIM + n0 + tx];
    __syncthreads();
    #pragma unroll
    for (int j = 0; j < 32; j += 8)
        Th[(size_t)(n0 + ty + j) * K_DIM + k0 + tx] = __float2half(t[tx][ty + j]);
}

// ---------------- score partials: 1024 blocks, 16 c-rows each ----------------
__global__ __launch_bounds__(256) void score_partial(
    const float* __restrict__ keys, const float* __restrict__ q,
    float* __restrict__ partial)
{
    const int n     = blockIdx.x * 256 + threadIdx.x;
    const int chunk = blockIdx.y;
    const int c0    = chunk * (L_DIM / NCHUNK);

    float s[NHEADS] = {0.f, 0.f, 0.f, 0.f};
    #pragma unroll 2
    for (int c = c0; c < c0 + L_DIM / NCHUNK; c++) {
        const float qv = __ldg(&q[(size_t)c * N_DIM + n]);
        #pragma unroll
        for (int h = 0; h < NHEADS; h++)
            s[h] += __ldg(&keys[((size_t)(h * L_DIM + c)) * N_DIM + n]) * qv;
    }
    #pragma unroll
    for (int h = 0; h < NHEADS; h++)
        partial[((size_t)chunk * NHEADS + h) * N_DIM + n] = s[h];
}

// ---------------- softmax over heads ----------------
__global__ __launch_bounds__(256) void softmax_heads(
    const float* __restrict__ partial, float* __restrict__ weight,
    float* __restrict__ wmap_out)
{
    int n = blockIdx.x * 256 + threadIdx.x;
    float s[NHEADS] = {0.f, 0.f, 0.f, 0.f};
    for (int ch = 0; ch < NCHUNK; ch++)
        #pragma unroll
        for (int h = 0; h < NHEADS; h++)
            s[h] += partial[((size_t)ch * NHEADS + h) * N_DIM + n];
    const float inv_sqrt_dk = 1.0f / 32.0f;
    float m = -1e30f;
    #pragma unroll
    for (int h = 0; h < NHEADS; h++) { s[h] *= inv_sqrt_dk; m = fmaxf(m, s[h]); }
    float e[NHEADS], sum = 0.f;
    #pragma unroll
    for (int h = 0; h < NHEADS; h++) { e[h] = __expf(s[h] - m); sum += e[h]; }
    float inv = 1.0f / sum;
    #pragma unroll
    for (int h = 0; h < NHEADS; h++) {
        float wv = e[h] * inv;
        weight[(size_t)h * N_DIM + n]   = wv;
        wmap_out[(size_t)h * N_DIM + n] = wv;
    }
}

// ---------------- z + residual + LayerNorm ----------------
__global__ __launch_bounds__(512) void z_layernorm(
    const float* __restrict__ keys, const float* __restrict__ q,
    const float* __restrict__ weight, const float* __restrict__ gamma,
    const float* __restrict__ beta, float* __restrict__ fused)
{
    const int c = blockIdx.x;
    __shared__ float r1[16], r2[16];
    __shared__ float s_mean, s_rstd;

    float v[2][4];
    float lsum = 0.f, lsq = 0.f;
    #pragma unroll
    for (int j = 0; j < 2; j++) {
        const int n4 = (j * 512 + threadIdx.x) * 4;
        float4 qa = *reinterpret_cast<const float4*>(&q[(size_t)c * N_DIM + n4]);
        v[j][0] = qa.x; v[j][1] = qa.y; v[j][2] = qa.z; v[j][3] = qa.w;
        #pragma unroll
        for (int h = 0; h < NHEADS; h++) {
            float4 kv = *reinterpret_cast<const float4*>(
                &keys[((size_t)(h * L_DIM + c)) * N_DIM + n4]);
            float4 wv = *reinterpret_cast<const float4*>(&weight[(size_t)h * N_DIM + n4]);
            v[j][0] += wv.x * kv.x; v[j][1] += wv.y * kv.y;
            v[j][2] += wv.z * kv.z; v[j][3] += wv.w * kv.w;
        }
        #pragma unroll
        for (int e = 0; e < 4; e++) { lsum += v[j][e]; lsq += v[j][e] * v[j][e]; }
    }
    #pragma unroll
    for (int o = 16; o > 0; o >>= 1) {
        lsum += __shfl_xor_sync(0xffffffffu, lsum, o);
        lsq  += __shfl_xor_sync(0xffffffffu, lsq, o);
    }
    const int wid = threadIdx.x >> 5, lid = threadIdx.x & 31;
    if (lid == 0) { r1[wid] = lsum; r2[wid] = lsq; }
    __syncthreads();
    if (threadIdx.x == 0) {
        float ts = 0.f, tq = 0.f;
        #pragma unroll
        for (int i = 0; i < 16; i++) { ts += r1[i]; tq += r2[i]; }
        float mean = ts * (1.0f / N_DIM);
        float var  = tq * (1.0f / N_DIM) - mean * mean;
        s_mean = mean;
        s_rstd = rsqrtf(var + 1e-5f);
    }
    __syncthreads();
    const float mean = s_mean, rstd = s_rstd;
    #pragma unroll
    for (int j = 0; j < 2; j++) {
        const int n4 = (j * 512 + threadIdx.x) * 4;
        float4 ga = *reinterpret_cast<const float4*>(&gamma[n4]);
        float4 ba = *reinterpret_cast<const float4*>(&beta[n4]);
        float4 o;
        o.x = (v[j][0] - mean) * rstd * ga.x + ba.x;
        o.y = (v[j][1] - mean) * rstd * ga.y + ba.y;
        o.z = (v[j][2] - mean) * rstd * ga.z + ba.z;
        o.w = (v[j][3] - mean) * rstd * ga.w + ba.w;
        *reinterpret_cast<float4*>(&fused[(size_t)c * N_DIM + n4]) = o;
    }
}

// ---------------- launch ----------------
extern "C" void kernel_launch(void* const* d_in, const int* in_sizes, int n_in,
                              void* d_out, int out_size)
{
    const float* point = (const float*)d_in[0];
    const float* img   = (const float*)d_in[1];
    const float* W_img = (const float*)d_in[2];
    const float* b_img = (const float*)d_in[3];
    const float* W_L   = (const float*)d_in[4];
    const float* b_L   = (const float*)d_in[5];
    const float* ln_g  = (const float*)d_in[6];
    const float* ln_b  = (const float*)d_in[7];
    const float* W_f   = (const float*)d_in[8];
    const float* b_f   = (const float*)d_in[9];

    float* out  = (float*)d_out;
    float* wmap = out + (size_t)L_DIM * N_DIM;

    float *q, *keys, *partial, *weight, *fused;
    cudaGetSymbolAddress((void**)&q,       g_q);
    cudaGetSymbolAddress((void**)&keys,    g_keys);
    cudaGetSymbolAddress((void**)&partial, g_partial);
    cudaGetSymbolAddress((void**)&weight,  g_weight);
    cudaGetSymbolAddress((void**)&fused,   g_fused);

    __half *WL, *WI, *WF, *PT, *IT, *FT;
    cudaGetSymbolAddress((void**)&WL, g_WL);
    cudaGetSymbolAddress((void**)&WI, g_Wimg);
    cudaGetSymbolAddress((void**)&WF, g_Wf);
    cudaGetSymbolAddress((void**)&PT, g_PT);
    cudaGetSymbolAddress((void**)&IT, g_IT);
    cudaGetSymbolAddress((void**)&FT, g_FT);

    cudaFuncSetAttribute(gemm_qk, cudaFuncAttributeMaxDynamicSharedMemorySize, GEMM_DSMEM);
    cudaFuncSetAttribute(gemm_f,  cudaFuncAttributeMaxDynamicSharedMemorySize, GEMM_DSMEM);

    convert_w<<<(6 * L_DIM * K_DIM) / 256, 256>>>(W_L, W_img, W_f, WL, WI, WF);

    trans_h2<<<dim3(N_DIM / 32, K_DIM / 32, 2), 256>>>(point, PT, img, IT);

    gemm_qk<<<dim3(N_DIM / GBN, 8 + 32), 256, GEMM_DSMEM>>>(
        WL, WI, PT, IT, b_L, b_img, q, keys);

    score_partial<<<dim3(N_DIM / 256, NCHUNK), 256>>>(keys, q, partial);
    softmax_heads<<<N_DIM / 256, 256>>>(partial, weight, wmap);
    z_layernorm<<<L_DIM, 512>>>(keys, q, weight, ln_g, ln_b, fused);

    trans_h1<<<dim3(N_DIM / 32, K_DIM / 32), 256>>>(fused, FT);

    gemm_f<<<dim3(N_DIM / GBN, L_DIM / GBM), 256, GEMM_DSMEM>>>(
        WF, FT, b_f, out);
}

// round 11
// speedup vs baseline: 2.5409x; 1.0502x over previous
#include <cuda_runtime.h>
#include <cuda_fp16.h>
#include <cstdint>

#define L_DIM 1024
#define N_DIM 4096
#define K_DIM 1024
#define NHEADS 4
#define NSCHUNK 8   // c-chunks of 128 per head (keys GEMM grid rows per head)

// ---------------- scratch (device globals; no allocs allowed) ----------------
__device__ float g_q[L_DIM * N_DIM];
__device__ float g_keys[NHEADS * L_DIM * N_DIM];
__device__ float g_partial[NHEADS * NSCHUNK * N_DIM];   // [32][4096]
__device__ float g_weight[NHEADS * N_DIM];
__device__ float g_fused[L_DIM * N_DIM];

__device__ __half g_WL[L_DIM * K_DIM];
__device__ __half g_Wimg[NHEADS * L_DIM * K_DIM];
__device__ __half g_Wf[L_DIM * K_DIM];
__device__ __half g_PT[N_DIM * K_DIM];
__device__ __half g_IT[N_DIM * K_DIM];
__device__ __half g_FT[N_DIM * K_DIM];

// ---------------- PTX helpers (sm_80-portable only) ----------------
__device__ __forceinline__ uint32_t smem_u32(const void* p) {
    uint32_t r;
    asm("{ .reg .u64 t; cvta.to.shared.u64 t, %1; cvt.u32.u64 %0, t; }" : "=r"(r) : "l"(p));
    return r;
}
__device__ __forceinline__ void cp16(uint32_t dst, const void* src) {
    asm volatile("cp.async.cg.shared.global [%0], [%1], 16;" :: "r"(dst), "l"(src) : "memory");
}
__device__ __forceinline__ void cp_commit() {
    asm volatile("cp.async.commit_group;" ::: "memory");
}
__device__ __forceinline__ void cp_wait1() {
    asm volatile("cp.async.wait_group 1;" ::: "memory");
}
__device__ __forceinline__ void cp_wait0() {
    asm volatile("cp.async.wait_group 0;" ::: "memory");
}
__device__ __forceinline__ void ldsm_x4(uint32_t& r0, uint32_t& r1, uint32_t& r2, uint32_t& r3,
                                        uint32_t addr) {
    asm volatile("ldmatrix.sync.aligned.m8n8.x4.shared.b16 {%0,%1,%2,%3}, [%4];"
                 : "=r"(r0), "=r"(r1), "=r"(r2), "=r"(r3) : "r"(addr));
}
__device__ __forceinline__ void mma_f16(float* c, const uint32_t* a, uint32_t b0, uint32_t b1) {
    asm volatile(
        "mma.sync.aligned.m16n8k16.row.col.f32.f16.f16.f32 "
        "{%0,%1,%2,%3}, {%4,%5,%6,%7}, {%8,%9}, {%0,%1,%2,%3};"
        : "+f"(c[0]), "+f"(c[1]), "+f"(c[2]), "+f"(c[3])
        : "r"(a[0]), "r"(a[1]), "r"(a[2]), "r"(a[3]), "r"(b0), "r"(b1));
}

// ---------------- fp16 single-pass mma.sync GEMM (3-stage ring, 2 CTAs/SM) ------------
#define GBM 128
#define GBN 128
#define GBK 64
#define OFF_A 0
#define OFF_B 16384
#define STAGE_B 32768
#define NSTAGE 3
#define GEMM_DSMEM (NSTAGE * STAGE_B)       // 96 KB -> 2 CTAs/SM
#define KSTAGES (K_DIM / GBK)               // 16

// SCORE: fuse per-tile score partials (sum_c C[c,n]*qbuf[c,n]) into the epilogue.
template <bool SCORE>
__device__ __forceinline__ void gemm_body(
    const __half* __restrict__ A, const __half* __restrict__ B,
    const float* __restrict__ bias, float* __restrict__ C,
    int bm, int bn,
    const float* __restrict__ qbuf, float* __restrict__ partial, int chunk_idx)
{
    extern __shared__ char sm_raw[];
    const uint32_t sbase = smem_u32(sm_raw);

    const int tid  = threadIdx.x;
    const int lane = tid & 31;
    const int wid  = tid >> 5;
    const int wm   = wid >> 1;
    const int wn   = wid & 1;

    int crow[4], ccol[4];
    uint32_t cdst[4];
    #pragma unroll
    for (int t = 0; t < 4; t++) {
        int idx = (t << 8) + tid;
        int r = idx >> 3, c = idx & 7;
        crow[t] = r; ccol[t] = c;
        cdst[t] = (uint32_t)((r << 7) + ((c ^ (r & 7)) << 4));
    }

    auto issue_stage = [&](int kstage, int buf) {
        const uint32_t sb = sbase + buf * STAGE_B;
        const int k0 = kstage * GBK;
        #pragma unroll
        for (int t = 0; t < 4; t++) {
            const int r = crow[t], c = ccol[t];
            cp16(sb + OFF_A + cdst[t], A + (size_t)(bm + r) * K_DIM + k0 + (c << 3));
            cp16(sb + OFF_B + cdst[t], B + (size_t)(bn + r) * K_DIM + k0 + (c << 3));
        }
    };

    float acc[2][8][4];
    #pragma unroll
    for (int m = 0; m < 2; m++)
        #pragma unroll
        for (int n = 0; n < 8; n++)
            #pragma unroll
            for (int v = 0; v < 4; v++)
                acc[m][n][v] = 0.0f;

    const int a_row0 = wm * 32 + (lane & 15);
    const int a_ch0  = lane >> 4;
    const int b_row0 = wn * 64 + ((lane >> 4) << 3) + (lane & 7);
    const int b_ch0  = (lane >> 3) & 1;

    issue_stage(0, 0); cp_commit();
    issue_stage(1, 1); cp_commit();

    int bc = 0;
    for (int i = 0; i < KSTAGES; i++) {
        if (i < KSTAGES - 1) cp_wait1(); else cp_wait0();
        __syncthreads();

        if (i + 2 < KSTAGES) {
            int bi = bc + 2; if (bi >= NSTAGE) bi -= NSTAGE;
            issue_stage(i + 2, bi);
            cp_commit();
        }

        const uint32_t st = sbase + bc * STAGE_B;
        #pragma unroll
        for (int ks = 0; ks < 4; ks++) {
            uint32_t ah[2][4], bh[4][4];
            #pragma unroll
            for (int mt = 0; mt < 2; mt++) {
                const int r = a_row0 + mt * 16;
                const int ch = ks * 2 + a_ch0;
                ldsm_x4(ah[mt][0], ah[mt][1], ah[mt][2], ah[mt][3],
                        st + OFF_A + (r << 7) + ((ch ^ (r & 7)) << 4));
            }
            #pragma unroll
            for (int np = 0; np < 4; np++) {
                const int r = b_row0 + np * 16;
                const int ch = ks * 2 + b_ch0;
                ldsm_x4(bh[np][0], bh[np][1], bh[np][2], bh[np][3],
                        st + OFF_B + (r << 7) + ((ch ^ (r & 7)) << 4));
            }
            #pragma unroll
            for (int mt = 0; mt < 2; mt++)
                #pragma unroll
                for (int np = 0; np < 4; np++) {
                    mma_f16(acc[mt][np * 2 + 0], ah[mt], bh[np][0], bh[np][1]);
                    mma_f16(acc[mt][np * 2 + 1], ah[mt], bh[np][2], bh[np][3]);
                }
        }
        bc = (bc + 1 == NSTAGE) ? 0 : bc + 1;
    }

    float s[16];
    if (SCORE) {
        #pragma unroll
        for (int j = 0; j < 16; j++) s[j] = 0.0f;
    }

    #pragma unroll
    for (int mt = 0; mt < 2; mt++) {
        const int row = bm + wm * 32 + mt * 16 + (lane >> 2);
        const float bv0 = bias[row], bv8 = bias[row + 8];
        const int c0 = row & (L_DIM - 1);          // c within head (SCORE path)
        #pragma unroll
        for (int nt = 0; nt < 8; nt++) {
            const int col = bn + wn * 64 + nt * 8 + (lane & 3) * 2;
            const float k00 = acc[mt][nt][0] + bv0, k01 = acc[mt][nt][1] + bv0;
            const float k80 = acc[mt][nt][2] + bv8, k81 = acc[mt][nt][3] + bv8;
            *reinterpret_cast<float2*>(&C[(size_t)row * N_DIM + col]) =
                make_float2(k00, k01);
            *reinterpret_cast<float2*>(&C[(size_t)(row + 8) * N_DIM + col]) =
                make_float2(k80, k81);
            if (SCORE) {
                const float2 q0 = *reinterpret_cast<const float2*>(
                    &qbuf[(size_t)c0 * N_DIM + col]);
                const float2 q8 = *reinterpret_cast<const float2*>(
                    &qbuf[(size_t)(c0 + 8) * N_DIM + col]);
                s[nt * 2 + 0] += k00 * q0.x + k80 * q8.x;
                s[nt * 2 + 1] += k01 * q0.y + k81 * q8.y;
            }
        }
    }

    if (SCORE) {
        // reduce over the 8 row-groups within the warp (lane>>2)
        #pragma unroll
        for (int j = 0; j < 16; j++) {
            s[j] += __shfl_xor_sync(0xffffffffu, s[j], 4);
            s[j] += __shfl_xor_sync(0xffffffffu, s[j], 8);
            s[j] += __shfl_xor_sync(0xffffffffu, s[j], 16);
        }
        __syncthreads();                      // stage smem now reusable
        float* sbuf = reinterpret_cast<float*>(sm_raw);   // [8 warps][128 cols]
        if ((lane >> 2) == 0) {
            #pragma unroll
            for (int nt = 0; nt < 8; nt++) {
                const int lc = wn * 64 + nt * 8 + (lane & 3) * 2;
                sbuf[wid * 128 + lc + 0] = s[nt * 2 + 0];
                sbuf[wid * 128 + lc + 1] = s[nt * 2 + 1];
            }
        }
        __syncthreads();
        if (tid < 128) {
            const int wn_ = tid >> 6;
            float tot = sbuf[(0 * 2 + wn_) * 128 + tid]
                      + sbuf[(1 * 2 + wn_) * 128 + tid]
                      + sbuf[(2 * 2 + wn_) * 128 + tid]
                      + sbuf[(3 * 2 + wn_) * 128 + tid];
            partial[(size_t)chunk_idx * N_DIM + bn + tid] = tot;
        }
    }
}

__global__ __launch_bounds__(256, 2) void gemm_q(
    const __half* __restrict__ WL, const __half* __restrict__ PT,
    const float* __restrict__ b_L, float* __restrict__ q)
{
    gemm_body<false>(WL, PT, b_L, q, blockIdx.y * GBM, blockIdx.x * GBN,
                     nullptr, nullptr, 0);
}

__global__ __launch_bounds__(256, 2) void gemm_keys(
    const __half* __restrict__ WI, const __half* __restrict__ IT,
    const float* __restrict__ b_img, float* __restrict__ keys,
    const float* __restrict__ q, float* __restrict__ partial)
{
    gemm_body<true>(WI, IT, b_img, keys, blockIdx.y * GBM, blockIdx.x * GBN,
                    q, partial, blockIdx.y);
}

__global__ __launch_bounds__(256, 2) void gemm_f(
    const __half* __restrict__ A, const __half* __restrict__ B,
    const float* __restrict__ bias, float* __restrict__ C)
{
    gemm_body<false>(A, B, bias, C, blockIdx.y * GBM, blockIdx.x * GBN,
                     nullptr, nullptr, 0);
}

// ---------------- fused weight convert (fp32 -> fp16, half2) ----------------
__global__ __launch_bounds__(256) void convert_w(
    const float* __restrict__ W_L, const float* __restrict__ W_img,
    const float* __restrict__ W_f,
    __half* __restrict__ WL, __half* __restrict__ WI, __half* __restrict__ WF)
{
    const int WSZ = L_DIM * K_DIM;
    int i = (blockIdx.x * 256 + threadIdx.x) * 2;
    const float* src; __half* dst; int off;
    if (i < WSZ)          { src = W_L;   dst = WL; off = i; }
    else if (i < 5 * WSZ) { src = W_img; dst = WI; off = i - WSZ; }
    else                  { src = W_f;   dst = WF; off = i - 5 * WSZ; }
    float2 v = *reinterpret_cast<const float2*>(src + off);
    *reinterpret_cast<__half2*>(dst + off) = __floats2half2_rn(v.x, v.y);
}

// ---------------- fp32 [K, N] -> fp16 [N, K] transpose ----------------
__global__ __launch_bounds__(256) void trans_h2(
    const float* __restrict__ X0, __half* __restrict__ T0,
    const float* __restrict__ X1, __half* __restrict__ T1)
{
    const float* X = (blockIdx.z == 0) ? X0 : X1;
    __half* Th = (blockIdx.z == 0) ? T0 : T1;
    __shared__ float t[32][33];
    int n0 = blockIdx.x * 32, k0 = blockIdx.y * 32;
    int tx = threadIdx.x & 31, ty = threadIdx.x >> 5;
    #pragma unroll
    for (int j = 0; j < 32; j += 8)
        t[ty + j][tx] = X[(size_t)(k0 + ty + j) * N_DIM + n0 + tx];
    __syncthreads();
    #pragma unroll
    for (int j = 0; j < 32; j += 8)
        Th[(size_t)(n0 + ty + j) * K_DIM + k0 + tx] = __float2half(t[tx][ty + j]);
}

__global__ __launch_bounds__(256) void trans_h1(
    const float* __restrict__ X, __half* __restrict__ Th)
{
    __shared__ float t[32][33];
    int n0 = blockIdx.x * 32, k0 = blockIdx.y * 32;
    int tx = threadIdx.x & 31, ty = threadIdx.x >> 5;
    #pragma unroll
    for (int j = 0; j < 32; j += 8)
        t[ty + j][tx] = X[(size_t)(k0 + ty + j) * N_DIM + n0 + tx];
    __syncthreads();
    #pragma unroll
    for (int j = 0; j < 32; j += 8)
        Th[(size_t)(n0 + ty + j) * K_DIM + k0 + tx] = __float2half(t[tx][ty + j]);
}

// ---------------- softmax over heads (8 c-chunk partials per head) ----------------
__global__ __launch_bounds__(256) void softmax_heads(
    const float* __restrict__ partial, float* __restrict__ weight,
    float* __restrict__ wmap_out)
{
    int n = blockIdx.x * 256 + threadIdx.x;             // gridDim.x = 16
    float s[NHEADS] = {0.f, 0.f, 0.f, 0.f};
    #pragma unroll
    for (int h = 0; h < NHEADS; h++)
        #pragma unroll
        for (int j = 0; j < NSCHUNK; j++)
            s[h] += partial[((size_t)(h * NSCHUNK + j)) * N_DIM + n];
    const float inv_sqrt_dk = 1.0f / 32.0f;
    float m = -1e30f;
    #pragma unroll
    for (int h = 0; h < NHEADS; h++) { s[h] *= inv_sqrt_dk; m = fmaxf(m, s[h]); }
    float e[NHEADS], sum = 0.f;
    #pragma unroll
    for (int h = 0; h < NHEADS; h++) { e[h] = __expf(s[h] - m); sum += e[h]; }
    float inv = 1.0f / sum;
    #pragma unroll
    for (int h = 0; h < NHEADS; h++) {
        float wv = e[h] * inv;
        weight[(size_t)h * N_DIM + n]   = wv;
        wmap_out[(size_t)h * N_DIM + n] = wv;
    }
}

// ---------------- z + residual + LayerNorm ----------------
__global__ __launch_bounds__(512) void z_layernorm(
    const float* __restrict__ keys, const float* __restrict__ q,
    const float* __restrict__ weight, const float* __restrict__ gamma,
    const float* __restrict__ beta, float* __restrict__ fused)
{
    const int c = blockIdx.x;
    __shared__ float r1[16], r2[16];
    __shared__ float s_mean, s_rstd;

    float v[2][4];
    float lsum = 0.f, lsq = 0.f;
    #pragma unroll
    for (int j = 0; j < 2; j++) {
        const int n4 = (j * 512 + threadIdx.x) * 4;
        float4 qa = *reinterpret_cast<const float4*>(&q[(size_t)c * N_DIM + n4]);
        v[j][0] = qa.x; v[j][1] = qa.y; v[j][2] = qa.z; v[j][3] = qa.w;
        #pragma unroll
        for (int h = 0; h < NHEADS; h++) {
            float4 kv = *reinterpret_cast<const float4*>(
                &keys[((size_t)(h * L_DIM + c)) * N_DIM + n4]);
            float4 wv = *reinterpret_cast<const float4*>(&weight[(size_t)h * N_DIM + n4]);
            v[j][0] += wv.x * kv.x; v[j][1] += wv.y * kv.y;
            v[j][2] += wv.z * kv.z; v[j][3] += wv.w * kv.w;
        }
        #pragma unroll
        for (int e = 0; e < 4; e++) { lsum += v[j][e]; lsq += v[j][e] * v[j][e]; }
    }
    #pragma unroll
    for (int o = 16; o > 0; o >>= 1) {
        lsum += __shfl_xor_sync(0xffffffffu, lsum, o);
        lsq  += __shfl_xor_sync(0xffffffffu, lsq, o);
    }
    const int wid = threadIdx.x >> 5, lid = threadIdx.x & 31;
    if (lid == 0) { r1[wid] = lsum; r2[wid] = lsq; }
    __syncthreads();
    if (threadIdx.x == 0) {
        float ts = 0.f, tq = 0.f;
        #pragma unroll
        for (int i = 0; i < 16; i++) { ts += r1[i]; tq += r2[i]; }
        float mean = ts * (1.0f / N_DIM);
        float var  = tq * (1.0f / N_DIM) - mean * mean;
        s_mean = mean;
        s_rstd = rsqrtf(var + 1e-5f);
    }
    __syncthreads();
    const float mean = s_mean, rstd = s_rstd;
    #pragma unroll
    for (int j = 0; j < 2; j++) {
        const int n4 = (j * 512 + threadIdx.x) * 4;
        float4 ga = *reinterpret_cast<const float4*>(&gamma[n4]);
        float4 ba = *reinterpret_cast<const float4*>(&beta[n4]);
        float4 o;
        o.x = (v[j][0] - mean) * rstd * ga.x + ba.x;
        o.y = (v[j][1] - mean) * rstd * ga.y + ba.y;
        o.z = (v[j][2] - mean) * rstd * ga.z + ba.z;
        o.w = (v[j][3] - mean) * rstd * ga.w + ba.w;
        *reinterpret_cast<float4*>(&fused[(size_t)c * N_DIM + n4]) = o;
    }
}

// ---------------- launch ----------------
extern "C" void kernel_launch(void* const* d_in, const int* in_sizes, int n_in,
                              void* d_out, int out_size)
{
    const float* point = (const float*)d_in[0];
    const float* img   = (const float*)d_in[1];
    const float* W_img = (const float*)d_in[2];
    const float* b_img = (const float*)d_in[3];
    const float* W_L   = (const float*)d_in[4];
    const float* b_L   = (const float*)d_in[5];
    const float* ln_g  = (const float*)d_in[6];
    const float* ln_b  = (const float*)d_in[7];
    const float* W_f   = (const float*)d_in[8];
    const float* b_f   = (const float*)d_in[9];

    float* out  = (float*)d_out;
    float* wmap = out + (size_t)L_DIM * N_DIM;

    float *q, *keys, *partial, *weight, *fused;
    cudaGetSymbolAddress((void**)&q,       g_q);
    cudaGetSymbolAddress((void**)&keys,    g_keys);
    cudaGetSymbolAddress((void**)&partial, g_partial);
    cudaGetSymbolAddress((void**)&weight,  g_weight);
    cudaGetSymbolAddress((void**)&fused,   g_fused);

    __half *WL, *WI, *WF, *PT, *IT, *FT;
    cudaGetSymbolAddress((void**)&WL, g_WL);
    cudaGetSymbolAddress((void**)&WI, g_Wimg);
    cudaGetSymbolAddress((void**)&WF, g_Wf);
    cudaGetSymbolAddress((void**)&PT, g_PT);
    cudaGetSymbolAddress((void**)&IT, g_IT);
    cudaGetSymbolAddress((void**)&FT, g_FT);

    cudaFuncSetAttribute(gemm_q,    cudaFuncAttributeMaxDynamicSharedMemorySize, GEMM_DSMEM);
    cudaFuncSetAttribute(gemm_keys, cudaFuncAttributeMaxDynamicSharedMemorySize, GEMM_DSMEM);
    cudaFuncSetAttribute(gemm_f,    cudaFuncAttributeMaxDynamicSharedMemorySize, GEMM_DSMEM);

    convert_w<<<(6 * L_DIM * K_DIM) / 512, 256>>>(W_L, W_img, W_f, WL, WI, WF);

    trans_h2<<<dim3(N_DIM / 32, K_DIM / 32, 2), 256>>>(point, PT, img, IT);

    // q must complete before the keys GEMM's score epilogue reads it
    gemm_q<<<dim3(N_DIM / GBN, L_DIM / GBM), 256, GEMM_DSMEM>>>(WL, PT, b_L, q);
    gemm_keys<<<dim3(N_DIM / GBN, (NHEADS * L_DIM) / GBM), 256, GEMM_DSMEM>>>(
        WI, IT, b_img, keys, q, partial);

    softmax_heads<<<N_DIM / 256, 256>>>(partial, weight, wmap);
    z_layernorm<<<L_DIM, 512>>>(keys, q, weight, ln_g, ln_b, fused);

    trans_h1<<<dim3(N_DIM / 32, K_DIM / 32), 256>>>(fused, FT);

    gemm_f<<<dim3(N_DIM / GBN, L_DIM / GBM), 256, GEMM_DSMEM>>>(WF, FT, b_f, out);
}